// round 1
// baseline (speedup 1.0000x reference)
#include <cuda_runtime.h>
#include <math.h>

#define NN 100000
#define NE 1600000
#define FIN 165
#define F1  256
#define EPSV 1e-16f

// ---------------- scratch (device globals; no allocations allowed) ----------
__device__ __align__(16) float    g_h1[(size_t)NN * F1];
__device__ __align__(16) float    g_out1[(size_t)NN * F1];
__device__ __align__(16) float    g_asrc1[NN * 4];
__device__ __align__(16) float    g_adst1[NN * 4];
__device__ __align__(16) unsigned g_m1[NN * 4];
__device__ __align__(16) float    g_s1[NN * 4];
__device__ __align__(16) float    g_g[NN * 2];
__device__ float    g_asrc2[NN];
__device__ float    g_adst2[NN];
__device__ unsigned g_m2[NN];
__device__ float    g_s2[NN];

// monotonic float<->uint encoding so atomicMax(unsigned) == float max
__device__ __forceinline__ unsigned fenc(float f) {
    unsigned b = __float_as_uint(f);
    return (b & 0x80000000u) ? ~b : (b | 0x80000000u);
}
__device__ __forceinline__ float fdec(unsigned u) {
    return __uint_as_float((u & 0x80000000u) ? (u & 0x7fffffffu) : ~u);
}
__device__ __forceinline__ float lrelu(float v) { return v > 0.f ? v : 0.2f * v; }

// ---------------- Layer 1: GEMM h1 = x @ W1  (M=N nodes, K=165, N=256) -----
__global__ void k_gemm1(const float* __restrict__ x, const float* __restrict__ W, int n) {
    __shared__ float As[16][65];
    __shared__ float Bs[16][68];
    int bm = blockIdx.y * 64;
    int bn = blockIdx.x * 64;
    int tid = threadIdx.x;
    int tx = tid & 15, ty = tid >> 4;

    float acc[4][4];
#pragma unroll
    for (int i = 0; i < 4; i++)
#pragma unroll
        for (int j = 0; j < 4; j++) acc[i][j] = 0.f;

    for (int k0 = 0; k0 < FIN; k0 += 16) {
        // load A tile: 64 rows x 16 k
        {
            int r = tid >> 2;
            int kq = (tid & 3) * 4;
            int row = bm + r;
#pragma unroll
            for (int i = 0; i < 4; i++) {
                int k = k0 + kq + i;
                As[kq + i][r] = (row < n && k < FIN) ? x[(size_t)row * FIN + k] : 0.f;
            }
        }
        // load B tile: 16 k x 64 cols
        {
            int kb = tid >> 4;
            int n4 = (tid & 15) * 4;
            int kk = k0 + kb;
            float4 bv = make_float4(0.f, 0.f, 0.f, 0.f);
            if (kk < FIN) bv = *(const float4*)(W + (size_t)kk * F1 + bn + n4);
            Bs[kb][n4 + 0] = bv.x; Bs[kb][n4 + 1] = bv.y;
            Bs[kb][n4 + 2] = bv.z; Bs[kb][n4 + 3] = bv.w;
        }
        __syncthreads();
#pragma unroll
        for (int kk = 0; kk < 16; kk++) {
            float a0 = As[kk][ty * 4 + 0], a1 = As[kk][ty * 4 + 1];
            float a2 = As[kk][ty * 4 + 2], a3 = As[kk][ty * 4 + 3];
            float b0 = Bs[kk][tx * 4 + 0], b1 = Bs[kk][tx * 4 + 1];
            float b2 = Bs[kk][tx * 4 + 2], b3 = Bs[kk][tx * 4 + 3];
            acc[0][0] += a0 * b0; acc[0][1] += a0 * b1; acc[0][2] += a0 * b2; acc[0][3] += a0 * b3;
            acc[1][0] += a1 * b0; acc[1][1] += a1 * b1; acc[1][2] += a1 * b2; acc[1][3] += a1 * b3;
            acc[2][0] += a2 * b0; acc[2][1] += a2 * b1; acc[2][2] += a2 * b2; acc[2][3] += a2 * b3;
            acc[3][0] += a3 * b0; acc[3][1] += a3 * b1; acc[3][2] += a3 * b2; acc[3][3] += a3 * b3;
        }
        __syncthreads();
    }
#pragma unroll
    for (int i = 0; i < 4; i++) {
        int row = bm + ty * 4 + i;
        if (row < n) {
            float4 v = make_float4(acc[i][0], acc[i][1], acc[i][2], acc[i][3]);
            *(float4*)(&g_h1[(size_t)row * F1 + bn + tx * 4]) = v;
        }
    }
}

// a_src1/a_dst1: per (node, head) dot over 64 channels
__global__ void k_scores1(const float* __restrict__ att_s, const float* __restrict__ att_d, int n) {
    __shared__ float sa[256], sd[256];
    for (int i = threadIdx.x; i < 256; i += blockDim.x) { sa[i] = att_s[i]; sd[i] = att_d[i]; }
    __syncthreads();
    int idx = blockIdx.x * blockDim.x + threadIdx.x;
    if (idx >= n * 4) return;
    int node = idx >> 2, h = idx & 3;
    const float* hp = &g_h1[(size_t)node * F1 + h * 64];
    float s = 0.f, d = 0.f;
#pragma unroll 8
    for (int c = 0; c < 64; c++) {
        float v = hp[c];
        s = fmaf(v, sa[h * 64 + c], s);
        d = fmaf(v, sd[h * 64 + c], d);
    }
    g_asrc1[idx] = s;
    g_adst1[idx] = d;
}

// init m1 with self-loop edge value
__global__ void k_initm1(int n) {
    int idx = blockIdx.x * blockDim.x + threadIdx.x;
    if (idx >= n * 4) return;
    g_m1[idx] = fenc(lrelu(g_asrc1[idx] + g_adst1[idx]));
}

__global__ void k_emax1(const int* __restrict__ src, const int* __restrict__ dst, int e) {
    int i = blockIdx.x * blockDim.x + threadIdx.x;
    if (i >= e) return;
    int s = src[i], d = dst[i];
    float4 a = *(const float4*)&g_asrc1[s * 4];
    float4 b = *(const float4*)&g_adst1[d * 4];
    atomicMax(&g_m1[d * 4 + 0], fenc(lrelu(a.x + b.x)));
    atomicMax(&g_m1[d * 4 + 1], fenc(lrelu(a.y + b.y)));
    atomicMax(&g_m1[d * 4 + 2], fenc(lrelu(a.z + b.z)));
    atomicMax(&g_m1[d * 4 + 3], fenc(lrelu(a.w + b.w)));
}

// init s1 with self-loop contribution
__global__ void k_inits1(int n) {
    int idx = blockIdx.x * blockDim.x + threadIdx.x;
    if (idx >= n * 4) return;
    float ev = lrelu(g_asrc1[idx] + g_adst1[idx]);
    g_s1[idx] = expf(ev - fdec(g_m1[idx]));
}

__global__ void k_esum1(const int* __restrict__ src, const int* __restrict__ dst, int e) {
    int i = blockIdx.x * blockDim.x + threadIdx.x;
    if (i >= e) return;
    int s = src[i], d = dst[i];
    float4 a = *(const float4*)&g_asrc1[s * 4];
    float4 b = *(const float4*)&g_adst1[d * 4];
    uint4  m = *(const uint4*)&g_m1[d * 4];
    atomicAdd(&g_s1[d * 4 + 0], expf(lrelu(a.x + b.x) - fdec(m.x)));
    atomicAdd(&g_s1[d * 4 + 1], expf(lrelu(a.y + b.y) - fdec(m.y)));
    atomicAdd(&g_s1[d * 4 + 2], expf(lrelu(a.z + b.z) - fdec(m.z)));
    atomicAdd(&g_s1[d * 4 + 3], expf(lrelu(a.w + b.w) - fdec(m.w)));
}

// init out1 with self-loop message
__global__ void k_initout1(int n) {
    int idx = blockIdx.x * blockDim.x + threadIdx.x;
    if (idx >= n * F1) return;
    int node = idx >> 8, c = idx & 255, h = c >> 6;
    int ih = node * 4 + h;
    float ev = lrelu(g_asrc1[ih] + g_adst1[ih]);
    float alpha = expf(ev - fdec(g_m1[ih])) / (g_s1[ih] + EPSV);
    g_out1[idx] = alpha * g_h1[idx];
}

// warp per edge: out1[dst] += alpha * h1[src]   (256 channels)
__global__ void k_emsg1(const int* __restrict__ src, const int* __restrict__ dst, int e) {
    int gtid = blockIdx.x * blockDim.x + threadIdx.x;
    int w = gtid >> 5, lane = gtid & 31;
    if (w >= e) return;
    int s = src[w], d = dst[w];
    int h = lane >> 3;
    int ih = d * 4 + h;
    float ev = lrelu(g_asrc1[s * 4 + h] + g_adst1[ih]);
    float alpha = expf(ev - fdec(g_m1[ih])) / (g_s1[ih] + EPSV);
    const float4* hp = (const float4*)&g_h1[(size_t)s * F1 + lane * 8];
    float* op = &g_out1[(size_t)d * F1 + lane * 8];
    float4 v0 = hp[0], v1 = hp[1];
    atomicAdd(op + 0, alpha * v0.x);
    atomicAdd(op + 1, alpha * v0.y);
    atomicAdd(op + 2, alpha * v0.z);
    atomicAdd(op + 3, alpha * v0.w);
    atomicAdd(op + 4, alpha * v1.x);
    atomicAdd(op + 5, alpha * v1.y);
    atomicAdd(op + 6, alpha * v1.z);
    atomicAdd(op + 7, alpha * v1.w);
}

// Layer 2 prep: warp per node: h2 = relu(out1 + b1); g = h2 @ W2; scores
__global__ void k_l2prep(const float* __restrict__ b1, const float* __restrict__ W2,
                         const float* __restrict__ as2, const float* __restrict__ ad2, int n) {
    __shared__ float sW[512];
    __shared__ float sb[256];
    for (int i = threadIdx.x; i < 512; i += blockDim.x) sW[i] = W2[i];
    for (int i = threadIdx.x; i < 256; i += blockDim.x) sb[i] = b1[i];
    __syncthreads();
    int w = (blockIdx.x * blockDim.x + threadIdx.x) >> 5;
    int lane = threadIdx.x & 31;
    if (w >= n) return;
    const float4* row = (const float4*)&g_out1[(size_t)w * F1];
    float g0 = 0.f, g1 = 0.f;
#pragma unroll
    for (int i = 0; i < 2; i++) {
        float4 v = row[lane * 2 + i];
        int c = lane * 8 + i * 4;
        float h0 = fmaxf(v.x + sb[c + 0], 0.f);
        float h1 = fmaxf(v.y + sb[c + 1], 0.f);
        float h2 = fmaxf(v.z + sb[c + 2], 0.f);
        float h3 = fmaxf(v.w + sb[c + 3], 0.f);
        g0 += h0 * sW[(c + 0) * 2] + h1 * sW[(c + 1) * 2] + h2 * sW[(c + 2) * 2] + h3 * sW[(c + 3) * 2];
        g1 += h0 * sW[(c + 0) * 2 + 1] + h1 * sW[(c + 1) * 2 + 1] + h2 * sW[(c + 2) * 2 + 1] + h3 * sW[(c + 3) * 2 + 1];
    }
#pragma unroll
    for (int o = 16; o; o >>= 1) {
        g0 += __shfl_down_sync(0xffffffffu, g0, o);
        g1 += __shfl_down_sync(0xffffffffu, g1, o);
    }
    if (lane == 0) {
        g_g[w * 2 + 0] = g0;
        g_g[w * 2 + 1] = g1;
        g_asrc2[w] = g0 * as2[0] + g1 * as2[1];
        g_adst2[w] = g0 * ad2[0] + g1 * ad2[1];
    }
}

__global__ void k_initm2(int n) {
    int i = blockIdx.x * blockDim.x + threadIdx.x;
    if (i >= n) return;
    g_m2[i] = fenc(lrelu(g_asrc2[i] + g_adst2[i]));
}

__global__ void k_emax2(const int* __restrict__ src, const int* __restrict__ dst, int e) {
    int i = blockIdx.x * blockDim.x + threadIdx.x;
    if (i >= e) return;
    int s = src[i], d = dst[i];
    atomicMax(&g_m2[d], fenc(lrelu(g_asrc2[s] + g_adst2[d])));
}

__global__ void k_inits2(int n) {
    int i = blockIdx.x * blockDim.x + threadIdx.x;
    if (i >= n) return;
    g_s2[i] = expf(lrelu(g_asrc2[i] + g_adst2[i]) - fdec(g_m2[i]));
}

__global__ void k_esum2(const int* __restrict__ src, const int* __restrict__ dst, int e) {
    int i = blockIdx.x * blockDim.x + threadIdx.x;
    if (i >= e) return;
    int s = src[i], d = dst[i];
    atomicAdd(&g_s2[d], expf(lrelu(g_asrc2[s] + g_adst2[d]) - fdec(g_m2[d])));
}

__global__ void k_initout2(float* __restrict__ out, int n) {
    int i = blockIdx.x * blockDim.x + threadIdx.x;
    if (i >= n) return;
    float ev = lrelu(g_asrc2[i] + g_adst2[i]);
    float alpha = expf(ev - fdec(g_m2[i])) / (g_s2[i] + EPSV);
    out[i * 2 + 0] = alpha * g_g[i * 2 + 0];
    out[i * 2 + 1] = alpha * g_g[i * 2 + 1];
}

__global__ void k_emsg2(const int* __restrict__ src, const int* __restrict__ dst,
                        float* __restrict__ out, int e) {
    int i = blockIdx.x * blockDim.x + threadIdx.x;
    if (i >= e) return;
    int s = src[i], d = dst[i];
    float ev = lrelu(g_asrc2[s] + g_adst2[d]);
    float alpha = expf(ev - fdec(g_m2[d])) / (g_s2[d] + EPSV);
    atomicAdd(&out[d * 2 + 0], alpha * g_g[s * 2 + 0]);
    atomicAdd(&out[d * 2 + 1], alpha * g_g[s * 2 + 1]);
}

__global__ void k_final(float* __restrict__ out, const float* __restrict__ b2, int n) {
    int i = blockIdx.x * blockDim.x + threadIdx.x;
    if (i >= n) return;
    float v0 = out[i * 2 + 0] + b2[0];
    float v1 = out[i * 2 + 1] + b2[1];
    float m = fmaxf(v0, v1);
    float l = logf(expf(v0 - m) + expf(v1 - m)) + m;
    out[i * 2 + 0] = v0 - l;
    out[i * 2 + 1] = v1 - l;
}

// ---------------------------------------------------------------------------
extern "C" void kernel_launch(void* const* d_in, const int* in_sizes, int n_in,
                              void* d_out, int out_size) {
    const float* x   = (const float*)d_in[0];
    const int*   src = (const int*)d_in[1];
    const int*   dst = (const int*)d_in[2];
    const float* W1  = (const float*)d_in[3];
    const float* as1 = (const float*)d_in[4];
    const float* ad1 = (const float*)d_in[5];
    const float* b1  = (const float*)d_in[6];
    const float* W2  = (const float*)d_in[7];
    const float* as2 = (const float*)d_in[8];
    const float* ad2 = (const float*)d_in[9];
    const float* b2  = (const float*)d_in[10];
    float* out = (float*)d_out;

    int n = in_sizes[0] / FIN;   // 100000
    int e = in_sizes[1];         // 1600000

    // Layer 1
    {
        dim3 grid((F1 + 63) / 64, (n + 63) / 64);
        k_gemm1<<<grid, 256>>>(x, W1, n);
    }
    k_scores1<<<(n * 4 + 255) / 256, 256>>>(as1, ad1, n);
    k_initm1<<<(n * 4 + 255) / 256, 256>>>(n);
    k_emax1<<<(e + 255) / 256, 256>>>(src, dst, e);
    k_inits1<<<(n * 4 + 255) / 256, 256>>>(n);
    k_esum1<<<(e + 255) / 256, 256>>>(src, dst, e);
    k_initout1<<<(n * F1 + 255) / 256, 256>>>(n);
    {
        long long threads = (long long)e * 32;
        int blocks = (int)((threads + 255) / 256);
        k_emsg1<<<blocks, 256>>>(src, dst, e);
    }

    // Layer 2
    k_l2prep<<<(n * 32 + 255) / 256, 256>>>(b1, W2, as2, ad2, n);
    k_initm2<<<(n + 255) / 256, 256>>>(n);
    k_emax2<<<(e + 255) / 256, 256>>>(src, dst, e);
    k_inits2<<<(n + 255) / 256, 256>>>(n);
    k_esum2<<<(e + 255) / 256, 256>>>(src, dst, e);
    k_initout2<<<(n + 255) / 256, 256>>>(out, n);
    k_emsg2<<<(e + 255) / 256, 256>>>(src, dst, out, e);
    k_final<<<(n + 255) / 256, 256>>>(out, b2, n);
}

// round 2
// speedup vs baseline: 3.7705x; 3.7705x over previous
#include <cuda_runtime.h>
#include <math.h>

#define NN 100000
#define NE 1600000
#define FIN 165
#define F1  256
#define EPSV 1e-16f

// ---------------- scratch (device globals; no allocations allowed) ----------
__device__ __align__(16) float g_h1[(size_t)NN * F1];
__device__ __align__(16) float g_out1[(size_t)NN * F1];
__device__ __align__(16) float g_asrc1[NN * 4];
__device__ __align__(16) float g_adst1[NN * 4];
__device__ __align__(16) float g_g[NN * 2];
__device__ float g_asrc2[NN];
__device__ float g_adst2[NN];
// CSR scratch
__device__ int g_cnt[NN];
__device__ int g_row[NN + 1];
__device__ int g_cur[NN];
__device__ int g_esrc[NE];

__device__ __forceinline__ float lrelu(float v) { return v > 0.f ? v : 0.2f * v; }

// ---------------- Layer 1: GEMM h1 = x @ W1  (M=N nodes, K=165, N=256) -----
__global__ void k_gemm1(const float* __restrict__ x, const float* __restrict__ W, int n) {
    __shared__ float As[16][65];
    __shared__ float Bs[16][68];
    int bm = blockIdx.y * 64;
    int bn = blockIdx.x * 64;
    int tid = threadIdx.x;
    int tx = tid & 15, ty = tid >> 4;

    float acc[4][4];
#pragma unroll
    for (int i = 0; i < 4; i++)
#pragma unroll
        for (int j = 0; j < 4; j++) acc[i][j] = 0.f;

    for (int k0 = 0; k0 < FIN; k0 += 16) {
        {
            int r = tid >> 2;
            int kq = (tid & 3) * 4;
            int row = bm + r;
#pragma unroll
            for (int i = 0; i < 4; i++) {
                int k = k0 + kq + i;
                As[kq + i][r] = (row < n && k < FIN) ? x[(size_t)row * FIN + k] : 0.f;
            }
        }
        {
            int kb = tid >> 4;
            int n4 = (tid & 15) * 4;
            int kk = k0 + kb;
            float4 bv = make_float4(0.f, 0.f, 0.f, 0.f);
            if (kk < FIN) bv = *(const float4*)(W + (size_t)kk * F1 + bn + n4);
            Bs[kb][n4 + 0] = bv.x; Bs[kb][n4 + 1] = bv.y;
            Bs[kb][n4 + 2] = bv.z; Bs[kb][n4 + 3] = bv.w;
        }
        __syncthreads();
#pragma unroll
        for (int kk = 0; kk < 16; kk++) {
            float a0 = As[kk][ty * 4 + 0], a1 = As[kk][ty * 4 + 1];
            float a2 = As[kk][ty * 4 + 2], a3 = As[kk][ty * 4 + 3];
            float b0 = Bs[kk][tx * 4 + 0], b1 = Bs[kk][tx * 4 + 1];
            float b2 = Bs[kk][tx * 4 + 2], b3 = Bs[kk][tx * 4 + 3];
            acc[0][0] += a0 * b0; acc[0][1] += a0 * b1; acc[0][2] += a0 * b2; acc[0][3] += a0 * b3;
            acc[1][0] += a1 * b0; acc[1][1] += a1 * b1; acc[1][2] += a1 * b2; acc[1][3] += a1 * b3;
            acc[2][0] += a2 * b0; acc[2][1] += a2 * b1; acc[2][2] += a2 * b2; acc[2][3] += a2 * b3;
            acc[3][0] += a3 * b0; acc[3][1] += a3 * b1; acc[3][2] += a3 * b2; acc[3][3] += a3 * b3;
        }
        __syncthreads();
    }
#pragma unroll
    for (int i = 0; i < 4; i++) {
        int row = bm + ty * 4 + i;
        if (row < n) {
            float4 v = make_float4(acc[i][0], acc[i][1], acc[i][2], acc[i][3]);
            *(float4*)(&g_h1[(size_t)row * F1 + bn + tx * 4]) = v;
        }
    }
}

// a_src1/a_dst1: per (node, head) dot over 64 channels
__global__ void k_scores1(const float* __restrict__ att_s, const float* __restrict__ att_d, int n) {
    __shared__ float sa[256], sd[256];
    for (int i = threadIdx.x; i < 256; i += blockDim.x) { sa[i] = att_s[i]; sd[i] = att_d[i]; }
    __syncthreads();
    int idx = blockIdx.x * blockDim.x + threadIdx.x;
    if (idx >= n * 4) return;
    int node = idx >> 2, h = idx & 3;
    const float* hp = &g_h1[(size_t)node * F1 + h * 64];
    float s = 0.f, d = 0.f;
#pragma unroll 8
    for (int c = 0; c < 64; c++) {
        float v = hp[c];
        s = fmaf(v, sa[h * 64 + c], s);
        d = fmaf(v, sd[h * 64 + c], d);
    }
    g_asrc1[idx] = s;
    g_adst1[idx] = d;
}

// ---------------- CSR build (group edges by dst) -----------------------------
__global__ void k_zerocnt(int n) {
    int i = blockIdx.x * blockDim.x + threadIdx.x;
    if (i < n) g_cnt[i] = 0;
}

__global__ void k_count(const int* __restrict__ dst, int e) {
    int i = blockIdx.x * blockDim.x + threadIdx.x;
    if (i < e) atomicAdd(&g_cnt[dst[i]], 1);
}

// single-block scan: g_row = exclusive prefix of g_cnt, g_row[n] = total
__global__ void k_scan(int n) {
    __shared__ int sh[1024];
    int t = threadIdx.x;
    int chunk = (n + 1023) / 1024;
    int b0 = t * chunk;
    int b1 = min(b0 + chunk, n);
    int sum = 0;
    for (int i = b0; i < b1; i++) sum += g_cnt[i];
    sh[t] = sum;
    __syncthreads();
    // Hillis-Steele inclusive scan
    for (int off = 1; off < 1024; off <<= 1) {
        int v = (t >= off) ? sh[t - off] : 0;
        __syncthreads();
        sh[t] += v;
        __syncthreads();
    }
    int run = (t > 0) ? sh[t - 1] : 0;
    for (int i = b0; i < b1; i++) {
        g_row[i] = run;
        run += g_cnt[i];
    }
    if (t == 1023) g_row[n] = sh[1023];
}

__global__ void k_copycur(int n) {
    int i = blockIdx.x * blockDim.x + threadIdx.x;
    if (i < n) g_cur[i] = g_row[i];
}

__global__ void k_scatter(const int* __restrict__ src, const int* __restrict__ dst, int e) {
    int i = blockIdx.x * blockDim.x + threadIdx.x;
    if (i >= e) return;
    int d = dst[i];
    int pos = atomicAdd(&g_cur[d], 1);
    g_esrc[pos] = src[i];
}

// ---------------- Layer 1 aggregation: warp per dst node, online softmax ----
__global__ void k_agg1(int n) {
    int w = (blockIdx.x * blockDim.x + threadIdx.x) >> 5;
    int lane = threadIdx.x & 31;
    if (w >= n) return;
    int h = lane >> 3;               // head for this lane (8 lanes per head)
    int ih = w * 4 + h;
    float adst = g_adst1[ih];

    // self-loop initializes the accumulator
    float m = lrelu(g_asrc1[ih] + adst);
    float s = 1.0f;
    float acc[8];
    {
        const float4* sp = (const float4*)&g_h1[(size_t)w * F1 + lane * 8];
        float4 v0 = __ldg(sp), v1 = __ldg(sp + 1);
        acc[0] = v0.x; acc[1] = v0.y; acc[2] = v0.z; acc[3] = v0.w;
        acc[4] = v1.x; acc[5] = v1.y; acc[6] = v1.z; acc[7] = v1.w;
    }

    int beg = g_row[w], end = g_row[w + 1];
    for (int i = beg; i < end; i++) {
        int sIdx = __ldg(&g_esrc[i]);
        float e = lrelu(__ldg(&g_asrc1[sIdx * 4 + h]) + adst);
        float newm = fmaxf(m, e);
        float scale = __expf(m - newm);
        float wgt = __expf(e - newm);
        s = s * scale + wgt;
        m = newm;
        const float4* hp = (const float4*)&g_h1[(size_t)sIdx * F1 + lane * 8];
        float4 u0 = __ldg(hp), u1 = __ldg(hp + 1);
        acc[0] = acc[0] * scale + wgt * u0.x;
        acc[1] = acc[1] * scale + wgt * u0.y;
        acc[2] = acc[2] * scale + wgt * u0.z;
        acc[3] = acc[3] * scale + wgt * u0.w;
        acc[4] = acc[4] * scale + wgt * u1.x;
        acc[5] = acc[5] * scale + wgt * u1.y;
        acc[6] = acc[6] * scale + wgt * u1.z;
        acc[7] = acc[7] * scale + wgt * u1.w;
    }
    float inv = 1.f / (s + EPSV);
    float* op = &g_out1[(size_t)w * F1 + lane * 8];
    float4 o0 = make_float4(acc[0] * inv, acc[1] * inv, acc[2] * inv, acc[3] * inv);
    float4 o1 = make_float4(acc[4] * inv, acc[5] * inv, acc[6] * inv, acc[7] * inv);
    *(float4*)(op) = o0;
    *(float4*)(op + 4) = o1;
}

// Layer 2 prep: warp per node: h2 = relu(out1 + b1); g = h2 @ W2; scores
__global__ void k_l2prep(const float* __restrict__ b1, const float* __restrict__ W2,
                         const float* __restrict__ as2, const float* __restrict__ ad2, int n) {
    __shared__ float sW[512];
    __shared__ float sb[256];
    for (int i = threadIdx.x; i < 512; i += blockDim.x) sW[i] = W2[i];
    for (int i = threadIdx.x; i < 256; i += blockDim.x) sb[i] = b1[i];
    __syncthreads();
    int w = (blockIdx.x * blockDim.x + threadIdx.x) >> 5;
    int lane = threadIdx.x & 31;
    if (w >= n) return;
    const float4* row = (const float4*)&g_out1[(size_t)w * F1];
    float g0 = 0.f, g1 = 0.f;
#pragma unroll
    for (int i = 0; i < 2; i++) {
        float4 v = row[lane * 2 + i];
        int c = lane * 8 + i * 4;
        float h0 = fmaxf(v.x + sb[c + 0], 0.f);
        float h1 = fmaxf(v.y + sb[c + 1], 0.f);
        float h2 = fmaxf(v.z + sb[c + 2], 0.f);
        float h3 = fmaxf(v.w + sb[c + 3], 0.f);
        g0 += h0 * sW[(c + 0) * 2] + h1 * sW[(c + 1) * 2] + h2 * sW[(c + 2) * 2] + h3 * sW[(c + 3) * 2];
        g1 += h0 * sW[(c + 0) * 2 + 1] + h1 * sW[(c + 1) * 2 + 1] + h2 * sW[(c + 2) * 2 + 1] + h3 * sW[(c + 3) * 2 + 1];
    }
#pragma unroll
    for (int o = 16; o; o >>= 1) {
        g0 += __shfl_down_sync(0xffffffffu, g0, o);
        g1 += __shfl_down_sync(0xffffffffu, g1, o);
    }
    if (lane == 0) {
        g_g[w * 2 + 0] = g0;
        g_g[w * 2 + 1] = g1;
        g_asrc2[w] = g0 * as2[0] + g1 * as2[1];
        g_adst2[w] = g0 * ad2[0] + g1 * ad2[1];
    }
}

// ---------------- Layer 2 aggregation + bias + log_softmax, fused -----------
__global__ void k_agg2(float* __restrict__ out, const float* __restrict__ b2, int n) {
    int w = (blockIdx.x * blockDim.x + threadIdx.x) >> 5;
    int lane = threadIdx.x & 31;
    if (w >= n) return;
    float adst = g_adst2[w];
    float m = -1e30f, s = 0.f, a0 = 0.f, a1 = 0.f;
    if (lane == 0) {   // self-loop
        m = lrelu(g_asrc2[w] + adst);
        s = 1.f;
        a0 = g_g[w * 2 + 0];
        a1 = g_g[w * 2 + 1];
    }
    int beg = g_row[w], end = g_row[w + 1];
    for (int i = beg + lane; i < end; i += 32) {
        int sIdx = __ldg(&g_esrc[i]);
        float e = lrelu(__ldg(&g_asrc2[sIdx]) + adst);
        float newm = fmaxf(m, e);
        float scale = __expf(m - newm);
        float wgt = __expf(e - newm);
        s = s * scale + wgt;
        a0 = a0 * scale + wgt * __ldg(&g_g[sIdx * 2 + 0]);
        a1 = a1 * scale + wgt * __ldg(&g_g[sIdx * 2 + 1]);
        m = newm;
    }
    // warp combine
#pragma unroll
    for (int o = 16; o; o >>= 1) {
        float m2 = __shfl_down_sync(0xffffffffu, m, o);
        float s2 = __shfl_down_sync(0xffffffffu, s, o);
        float b0 = __shfl_down_sync(0xffffffffu, a0, o);
        float b1 = __shfl_down_sync(0xffffffffu, a1, o);
        float newm = fmaxf(m, m2);
        float sc1 = __expf(m - newm);
        float sc2 = __expf(m2 - newm);
        s = s * sc1 + s2 * sc2;
        a0 = a0 * sc1 + b0 * sc2;
        a1 = a1 * sc1 + b1 * sc2;
        m = newm;
    }
    if (lane == 0) {
        float inv = 1.f / (s + EPSV);
        float v0 = a0 * inv + b2[0];
        float v1 = a1 * inv + b2[1];
        float mm = fmaxf(v0, v1);
        float l = logf(expf(v0 - mm) + expf(v1 - mm)) + mm;
        out[w * 2 + 0] = v0 - l;
        out[w * 2 + 1] = v1 - l;
    }
}

// ---------------------------------------------------------------------------
extern "C" void kernel_launch(void* const* d_in, const int* in_sizes, int n_in,
                              void* d_out, int out_size) {
    const float* x   = (const float*)d_in[0];
    const int*   src = (const int*)d_in[1];
    const int*   dst = (const int*)d_in[2];
    const float* W1  = (const float*)d_in[3];
    const float* as1 = (const float*)d_in[4];
    const float* ad1 = (const float*)d_in[5];
    const float* b1  = (const float*)d_in[6];
    const float* W2  = (const float*)d_in[7];
    const float* as2 = (const float*)d_in[8];
    const float* ad2 = (const float*)d_in[9];
    const float* b2  = (const float*)d_in[10];
    float* out = (float*)d_out;

    int n = in_sizes[0] / FIN;   // 100000
    int e = in_sizes[1];         // 1600000

    // CSR build (independent of GEMM; launch first so it overlaps nothing but is cheap)
    k_zerocnt<<<(n + 255) / 256, 256>>>(n);
    k_count<<<(e + 255) / 256, 256>>>(dst, e);
    k_scan<<<1, 1024>>>(n);
    k_copycur<<<(n + 255) / 256, 256>>>(n);
    k_scatter<<<(e + 255) / 256, 256>>>(src, dst, e);

    // Layer 1
    {
        dim3 grid((F1 + 63) / 64, (n + 63) / 64);
        k_gemm1<<<grid, 256>>>(x, W1, n);
    }
    k_scores1<<<(n * 4 + 255) / 256, 256>>>(as1, ad1, n);
    k_agg1<<<(n * 32 + 255) / 256, 256>>>(n);

    // Layer 2
    k_l2prep<<<(n * 32 + 255) / 256, 256>>>(b1, W2, as2, ad2, n);
    k_agg2<<<(n * 32 + 255) / 256, 256>>>(out, b2, n);
}

// round 3
// speedup vs baseline: 5.6114x; 1.4882x over previous
#include <cuda_runtime.h>
#include <cuda_bf16.h>
#include <math.h>
#include <stdint.h>

#define NN 100000
#define NE 1600000
#define FIN 165
#define F1  256
#define KP  176            // K padded to multiple of 16
#define KPW (KP/2)         // 32-bit words per row
#define EPSV 1e-16f

// ---------------- scratch (device globals; no allocations allowed) ----------
__device__ __align__(16) float g_h1[(size_t)NN * F1];
__device__ __align__(16) float g_asrc1[NN * 4];
__device__ __align__(16) float g_adst1[NN * 4];
__device__ __align__(16) float g_g[NN * 2];
__device__ float g_asrc2[NN];
__device__ float g_adst2[NN];
// bf16 split operands
__device__ __align__(16) __nv_bfloat16 g_xhi[(size_t)NN * KP];
__device__ __align__(16) __nv_bfloat16 g_xlo[(size_t)NN * KP];
__device__ __align__(16) __nv_bfloat16 g_whiT[256 * KP];
__device__ __align__(16) __nv_bfloat16 g_wloT[256 * KP];
// CSR scratch
__device__ int g_cnt[NN];
__device__ int g_row[NN + 1];
__device__ int g_cur[NN];
__device__ int g_esrc[NE];
__device__ int g_bsum[256];
__device__ int g_boff[256];

__device__ __forceinline__ float lrelu(float v) { return v > 0.f ? v : 0.2f * v; }

// ---------------- operand conversion (fp32 -> bf16 hi/lo, padded) ----------
__global__ void k_cvtx(const float* __restrict__ x, int n) {
    int i = blockIdx.x * blockDim.x + threadIdx.x;
    if (i >= n * KP) return;
    int node = i / KP, k = i - node * KP;
    float v = (k < FIN) ? x[(size_t)node * FIN + k] : 0.f;
    __nv_bfloat16 hi = __float2bfloat16(v);
    g_xhi[i] = hi;
    g_xlo[i] = __float2bfloat16(v - __bfloat162float(hi));
}

__global__ void k_cvtw(const float* __restrict__ W) {
    int i = blockIdx.x * blockDim.x + threadIdx.x;
    if (i >= 256 * KP) return;
    int nc = i / KP, k = i - nc * KP;
    float v = (k < FIN) ? W[(size_t)k * 256 + nc] : 0.f;
    __nv_bfloat16 hi = __float2bfloat16(v);
    g_whiT[i] = hi;
    g_wloT[i] = __float2bfloat16(v - __bfloat162float(hi));
}

// ---------------- tensor-core GEMM1 + fused attention scores ----------------
__device__ __forceinline__ void hmma(float* d, const uint32_t* a, const uint32_t* b) {
    asm volatile(
        "mma.sync.aligned.m16n8k16.row.col.f32.bf16.bf16.f32 "
        "{%0,%1,%2,%3},{%4,%5,%6,%7},{%8,%9},{%0,%1,%2,%3};\n"
        : "+f"(d[0]), "+f"(d[1]), "+f"(d[2]), "+f"(d[3])
        : "r"(a[0]), "r"(a[1]), "r"(a[2]), "r"(a[3]), "r"(b[0]), "r"(b[1]));
}

// block: 128 nodes x 64 cols (= one head). 256 threads = 8 warps (4m x 2n).
__global__ void k_gemm1_mma(const float* __restrict__ att_s, const float* __restrict__ att_d, int n) {
    __shared__ uint32_t sAhi[1024], sAlo[1024], sBhi[512], sBlo[512];
    __shared__ float sS[128], sD[128];
    int bm = blockIdx.y * 128, bn = blockIdx.x * 64, h = bn >> 6;
    int tid = threadIdx.x, lane = tid & 31, wid = tid >> 5;
    int wm = wid & 3, wn = wid >> 2, quad = lane >> 2, t4 = lane & 3;
    if (tid < 128) { sS[tid] = 0.f; sD[tid] = 0.f; }

    const uint32_t* xhi = (const uint32_t*)g_xhi;
    const uint32_t* xlo = (const uint32_t*)g_xlo;
    const uint32_t* whi = (const uint32_t*)g_whiT;
    const uint32_t* wlo = (const uint32_t*)g_wloT;

    float d[2][4][4];
#pragma unroll
    for (int a = 0; a < 2; a++)
#pragma unroll
        for (int b = 0; b < 4; b++)
#pragma unroll
            for (int c = 0; c < 4; c++) d[a][b][c] = 0.f;

    for (int k0 = 0; k0 < KP; k0 += 16) {
        int kw = k0 >> 1;
#pragma unroll
        for (int u = 0; u < 4; u++) {           // A: 128 rows x 8 kwords
            int wd = tid + u * 256;
            int row = wd >> 3, kp = wd & 7;
            int node = bm + row;
            uint32_t vh = 0, vl = 0;
            if (node < n) {
                size_t gi = (size_t)node * KPW + kw + kp;
                vh = xhi[gi]; vl = xlo[gi];
            }
            sAhi[wd] = vh; sAlo[wd] = vl;
        }
#pragma unroll
        for (int u = 0; u < 2; u++) {           // B: 64 cols x 8 kwords
            int wd = tid + u * 256;
            int nr = wd >> 3, kp = wd & 7;
            size_t gi = (size_t)(bn + nr) * KPW + kw + kp;
            sBhi[wd] = whi[gi]; sBlo[wd] = wlo[gi];
        }
        __syncthreads();

        uint32_t ah[2][4], al[2][4], bh[4][2], bl[4][2];
#pragma unroll
        for (int mt = 0; mt < 2; mt++) {
            int r0 = (wm * 32 + mt * 16 + quad) * 8;
            // a0:(g,k) a1:(g+8,k) a2:(g,k+8) a3:(g+8,k+8)
            ah[mt][0] = sAhi[r0 + t4];       ah[mt][1] = sAhi[r0 + 64 + t4];
            ah[mt][2] = sAhi[r0 + t4 + 4];   ah[mt][3] = sAhi[r0 + 64 + t4 + 4];
            al[mt][0] = sAlo[r0 + t4];       al[mt][1] = sAlo[r0 + 64 + t4];
            al[mt][2] = sAlo[r0 + t4 + 4];   al[mt][3] = sAlo[r0 + 64 + t4 + 4];
        }
#pragma unroll
        for (int nt = 0; nt < 4; nt++) {
            int c0 = (wn * 32 + nt * 8 + quad) * 8;
            bh[nt][0] = sBhi[c0 + t4]; bh[nt][1] = sBhi[c0 + t4 + 4];
            bl[nt][0] = sBlo[c0 + t4]; bl[nt][1] = sBlo[c0 + t4 + 4];
        }
#pragma unroll
        for (int mt = 0; mt < 2; mt++)
#pragma unroll
            for (int nt = 0; nt < 4; nt++) {
                hmma(d[mt][nt], ah[mt], bh[nt]);
                hmma(d[mt][nt], ah[mt], bl[nt]);
                hmma(d[mt][nt], al[mt], bh[nt]);
            }
        __syncthreads();
    }

    // store h1 + accumulate attention-score partial dots
#pragma unroll
    for (int mt = 0; mt < 2; mt++) {
        int row = wm * 32 + mt * 16 + quad;
        int node0 = bm + row, node1 = node0 + 8;
        float s0 = 0.f, s1 = 0.f, dd0 = 0.f, dd1 = 0.f;
#pragma unroll
        for (int nt = 0; nt < 4; nt++) {
            int c = wn * 32 + nt * 8 + t4 * 2;
            float a0 = __ldg(&att_s[h * 64 + c]), a1 = __ldg(&att_s[h * 64 + c + 1]);
            float e0 = __ldg(&att_d[h * 64 + c]), e1 = __ldg(&att_d[h * 64 + c + 1]);
            s0  += d[mt][nt][0] * a0 + d[mt][nt][1] * a1;
            dd0 += d[mt][nt][0] * e0 + d[mt][nt][1] * e1;
            s1  += d[mt][nt][2] * a0 + d[mt][nt][3] * a1;
            dd1 += d[mt][nt][2] * e0 + d[mt][nt][3] * e1;
            if (node0 < n)
                *(float2*)&g_h1[(size_t)node0 * F1 + bn + c] = make_float2(d[mt][nt][0], d[mt][nt][1]);
            if (node1 < n)
                *(float2*)&g_h1[(size_t)node1 * F1 + bn + c] = make_float2(d[mt][nt][2], d[mt][nt][3]);
        }
        // reduce across t4 lanes (same row)
        s0  += __shfl_xor_sync(0xffffffffu, s0, 1);  s0  += __shfl_xor_sync(0xffffffffu, s0, 2);
        s1  += __shfl_xor_sync(0xffffffffu, s1, 1);  s1  += __shfl_xor_sync(0xffffffffu, s1, 2);
        dd0 += __shfl_xor_sync(0xffffffffu, dd0, 1); dd0 += __shfl_xor_sync(0xffffffffu, dd0, 2);
        dd1 += __shfl_xor_sync(0xffffffffu, dd1, 1); dd1 += __shfl_xor_sync(0xffffffffu, dd1, 2);
        if (t4 == 0) {
            atomicAdd(&sS[row], s0); atomicAdd(&sD[row], dd0);
            atomicAdd(&sS[row + 8], s1); atomicAdd(&sD[row + 8], dd1);
        }
    }
    __syncthreads();
    if (tid < 128) {
        int node = bm + tid;
        if (node < n) {
            g_asrc1[node * 4 + h] = sS[tid];
            g_adst1[node * 4 + h] = sD[tid];
        }
    }
}

// ---------------- CSR build (group edges by dst) -----------------------------
__global__ void k_zerocnt(int n) {
    int i = blockIdx.x * blockDim.x + threadIdx.x;
    if (i < n) g_cnt[i] = 0;
}

__global__ void k_count(const int* __restrict__ dst, int e) {
    int i = blockIdx.x * blockDim.x + threadIdx.x;
    if (i < e) atomicAdd(&g_cnt[dst[i]], 1);
}

__global__ void k_scan1(int n) {
    __shared__ int sh[512];
    int t = threadIdx.x, i = blockIdx.x * 512 + t;
    sh[t] = (i < n) ? g_cnt[i] : 0;
    __syncthreads();
    for (int o = 256; o; o >>= 1) {
        if (t < o) sh[t] += sh[t + o];
        __syncthreads();
    }
    if (t == 0) g_bsum[blockIdx.x] = sh[0];
}

__global__ void k_scan2(int n, int nb) {
    __shared__ int sh[256];
    int t = threadIdx.x;
    int own = (t < nb) ? g_bsum[t] : 0;
    sh[t] = own;
    __syncthreads();
    for (int o = 1; o < 256; o <<= 1) {
        int v = (t >= o) ? sh[t - o] : 0;
        __syncthreads();
        sh[t] += v;
        __syncthreads();
    }
    if (t < nb) g_boff[t] = sh[t] - own;
    if (t == nb - 1) g_row[n] = sh[t];
}

__global__ void k_scan3(int n) {
    __shared__ int sh[512];
    int t = threadIdx.x, i = blockIdx.x * 512 + t;
    int own = (i < n) ? g_cnt[i] : 0;
    sh[t] = own;
    __syncthreads();
    for (int o = 1; o < 512; o <<= 1) {
        int v = (t >= o) ? sh[t - o] : 0;
        __syncthreads();
        sh[t] += v;
        __syncthreads();
    }
    if (i < n) {
        int excl = sh[t] - own + g_boff[blockIdx.x];
        g_row[i] = excl;
        g_cur[i] = excl;
    }
}

__global__ void k_scatter(const int* __restrict__ src, const int* __restrict__ dst, int e) {
    int i = blockIdx.x * blockDim.x + threadIdx.x;
    if (i >= e) return;
    int d = dst[i];
    int pos = atomicAdd(&g_cur[d], 1);
    g_esrc[pos] = src[i];
}

// ---- Layer-1 aggregation (online softmax) + fused relu/bias/GEMM2/scores ---
__global__ void k_agg1f(const float* __restrict__ b1, const float* __restrict__ W2,
                        const float* __restrict__ as2, const float* __restrict__ ad2, int n) {
    int w = (blockIdx.x * blockDim.x + threadIdx.x) >> 5;
    int lane = threadIdx.x & 31;
    if (w >= n) return;
    int h = lane >> 3;
    int ih = w * 4 + h;
    float adst = g_adst1[ih];

    float m = lrelu(g_asrc1[ih] + adst);
    float s = 1.0f;
    float acc[8];
    {
        const float4* sp = (const float4*)&g_h1[(size_t)w * F1 + lane * 8];
        float4 v0 = __ldg(sp), v1 = __ldg(sp + 1);
        acc[0] = v0.x; acc[1] = v0.y; acc[2] = v0.z; acc[3] = v0.w;
        acc[4] = v1.x; acc[5] = v1.y; acc[6] = v1.z; acc[7] = v1.w;
    }
    int beg = g_row[w], end = g_row[w + 1];
    for (int i = beg; i < end; i++) {
        int sIdx = __ldg(&g_esrc[i]);
        float e = lrelu(__ldg(&g_asrc1[sIdx * 4 + h]) + adst);
        float newm = fmaxf(m, e);
        float scale = __expf(m - newm);
        float wgt = __expf(e - newm);
        s = s * scale + wgt;
        m = newm;
        const float4* hp = (const float4*)&g_h1[(size_t)sIdx * F1 + lane * 8];
        float4 u0 = __ldg(hp), u1 = __ldg(hp + 1);
        acc[0] = acc[0] * scale + wgt * u0.x;
        acc[1] = acc[1] * scale + wgt * u0.y;
        acc[2] = acc[2] * scale + wgt * u0.z;
        acc[3] = acc[3] * scale + wgt * u0.w;
        acc[4] = acc[4] * scale + wgt * u1.x;
        acc[5] = acc[5] * scale + wgt * u1.y;
        acc[6] = acc[6] * scale + wgt * u1.z;
        acc[7] = acc[7] * scale + wgt * u1.w;
    }
    float inv = 1.f / (s + EPSV);
    // fused: h2 = relu(out1 + b1); g = h2 @ W2
    float g0 = 0.f, g1 = 0.f;
#pragma unroll
    for (int j = 0; j < 8; j++) {
        int c = lane * 8 + j;
        float hv = fmaxf(acc[j] * inv + __ldg(&b1[c]), 0.f);
        g0 = fmaf(hv, __ldg(&W2[c * 2 + 0]), g0);
        g1 = fmaf(hv, __ldg(&W2[c * 2 + 1]), g1);
    }
#pragma unroll
    for (int o = 16; o; o >>= 1) {
        g0 += __shfl_down_sync(0xffffffffu, g0, o);
        g1 += __shfl_down_sync(0xffffffffu, g1, o);
    }
    if (lane == 0) {
        g_g[w * 2 + 0] = g0;
        g_g[w * 2 + 1] = g1;
        g_asrc2[w] = g0 * __ldg(&as2[0]) + g1 * __ldg(&as2[1]);
        g_adst2[w] = g0 * __ldg(&ad2[0]) + g1 * __ldg(&ad2[1]);
    }
}

// ---------------- Layer 2 aggregation + bias + log_softmax, fused -----------
__global__ void k_agg2(float* __restrict__ out, const float* __restrict__ b2, int n) {
    int w = (blockIdx.x * blockDim.x + threadIdx.x) >> 5;
    int lane = threadIdx.x & 31;
    if (w >= n) return;
    float adst = g_adst2[w];
    float m = -1e30f, s = 0.f, a0 = 0.f, a1 = 0.f;
    if (lane == 0) {   // self-loop
        m = lrelu(g_asrc2[w] + adst);
        s = 1.f;
        a0 = g_g[w * 2 + 0];
        a1 = g_g[w * 2 + 1];
    }
    int beg = g_row[w], end = g_row[w + 1];
    for (int i = beg + lane; i < end; i += 32) {
        int sIdx = __ldg(&g_esrc[i]);
        float e = lrelu(__ldg(&g_asrc2[sIdx]) + adst);
        float newm = fmaxf(m, e);
        float scale = __expf(m - newm);
        float wgt = __expf(e - newm);
        s = s * scale + wgt;
        a0 = a0 * scale + wgt * __ldg(&g_g[sIdx * 2 + 0]);
        a1 = a1 * scale + wgt * __ldg(&g_g[sIdx * 2 + 1]);
        m = newm;
    }
#pragma unroll
    for (int o = 16; o; o >>= 1) {
        float m2 = __shfl_down_sync(0xffffffffu, m, o);
        float s2 = __shfl_down_sync(0xffffffffu, s, o);
        float b0 = __shfl_down_sync(0xffffffffu, a0, o);
        float b1 = __shfl_down_sync(0xffffffffu, a1, o);
        float newm = fmaxf(m, m2);
        float sc1 = __expf(m - newm);
        float sc2 = __expf(m2 - newm);
        s = s * sc1 + s2 * sc2;
        a0 = a0 * sc1 + b0 * sc2;
        a1 = a1 * sc1 + b1 * sc2;
        m = newm;
    }
    if (lane == 0) {
        float inv = 1.f / (s + EPSV);
        float v0 = a0 * inv + b2[0];
        float v1 = a1 * inv + b2[1];
        float mm = fmaxf(v0, v1);
        float l = logf(expf(v0 - mm) + expf(v1 - mm)) + mm;
        out[w * 2 + 0] = v0 - l;
        out[w * 2 + 1] = v1 - l;
    }
}

// ---------------------------------------------------------------------------
struct GpuSetup {
    cudaStream_t s2;
    cudaEvent_t eFork, eJoin;
    GpuSetup() {
        cudaStreamCreateWithFlags(&s2, cudaStreamNonBlocking);
        cudaEventCreateWithFlags(&eFork, cudaEventDisableTiming);
        cudaEventCreateWithFlags(&eJoin, cudaEventDisableTiming);
    }
};
static GpuSetup g_setup;

extern "C" void kernel_launch(void* const* d_in, const int* in_sizes, int n_in,
                              void* d_out, int out_size) {
    const float* x   = (const float*)d_in[0];
    const int*   src = (const int*)d_in[1];
    const int*   dst = (const int*)d_in[2];
    const float* W1  = (const float*)d_in[3];
    const float* as1 = (const float*)d_in[4];
    const float* ad1 = (const float*)d_in[5];
    const float* b1  = (const float*)d_in[6];
    const float* W2  = (const float*)d_in[7];
    const float* as2 = (const float*)d_in[8];
    const float* ad2 = (const float*)d_in[9];
    const float* b2  = (const float*)d_in[10];
    float* out = (float*)d_out;

    int n = in_sizes[0] / FIN;   // 100000
    int e = in_sizes[1];         // 1600000
    int nb = (n + 511) / 512;    // scan blocks

    // fork: CSR build on side stream, overlapped with convert+GEMM
    cudaEventRecord(g_setup.eFork, 0);
    cudaStreamWaitEvent(g_setup.s2, g_setup.eFork, 0);

    k_zerocnt<<<(n + 255) / 256, 256, 0, g_setup.s2>>>(n);
    k_count<<<(e + 255) / 256, 256, 0, g_setup.s2>>>(dst, e);
    k_scan1<<<nb, 512, 0, g_setup.s2>>>(n);
    k_scan2<<<1, 256, 0, g_setup.s2>>>(n, nb);
    k_scan3<<<nb, 512, 0, g_setup.s2>>>(n);
    k_scatter<<<(e + 255) / 256, 256, 0, g_setup.s2>>>(src, dst, e);
    cudaEventRecord(g_setup.eJoin, g_setup.s2);

    // main stream: bf16 conversion + tensor-core GEMM + fused scores
    k_cvtx<<<(n * KP + 255) / 256, 256>>>(x, n);
    k_cvtw<<<(256 * KP + 255) / 256, 256>>>(W1);
    {
        dim3 grid(4, (n + 127) / 128);
        k_gemm1_mma<<<grid, 256>>>(as1, ad1, n);
    }

    cudaStreamWaitEvent(0, g_setup.eJoin, 0);

    k_agg1f<<<(n * 32 + 255) / 256, 256>>>(b1, W2, as2, ad2, n);
    k_agg2<<<(n * 32 + 255) / 256, 256>>>(out, b2, n);
}

// round 4
// speedup vs baseline: 5.8016x; 1.0339x over previous
#include <cuda_runtime.h>
#include <cuda_bf16.h>
#include <cuda_fp16.h>
#include <math.h>
#include <stdint.h>

#define NN 100000
#define NE 1600000
#define FIN 165
#define F1  256
#define KP  176            // K padded to multiple of 16
#define KPW (KP/2)         // 32-bit words per row
#define EPSV 1e-16f

// ---------------- scratch (device globals; no allocations allowed) ----------
__device__ __align__(16) __half g_h1h[(size_t)NN * F1];   // fp16 h1 (51 MB)
__device__ __align__(16) float g_asrc1[NN * 4];
__device__ __align__(16) float g_adst1[NN * 4];
__device__ __align__(16) float g_m1[NN * 4];
__device__ __align__(16) float g_inv1[NN * 4];
__device__ __align__(16) float g_g[NN * 2];
__device__ float g_asrc2[NN];
__device__ float g_adst2[NN];
// bf16 split operands
__device__ __align__(16) __nv_bfloat16 g_xhi[(size_t)NN * KP];
__device__ __align__(16) __nv_bfloat16 g_xlo[(size_t)NN * KP];
__device__ __align__(16) __nv_bfloat16 g_whiT[256 * KP];
__device__ __align__(16) __nv_bfloat16 g_wloT[256 * KP];
// CSR scratch
__device__ int g_cnt[NN];
__device__ int g_row[NN + 1];
__device__ int g_cur[NN];
__device__ int g_esrc[NE];
__device__ int g_bsum[256];
__device__ int g_boff[256];

__device__ __forceinline__ float lrelu(float v) { return v > 0.f ? v : 0.2f * v; }

// ---------------- operand conversion (fp32 -> bf16 hi/lo, padded) ----------
__global__ void k_cvtx(const float* __restrict__ x, int n) {
    int i = blockIdx.x * blockDim.x + threadIdx.x;
    if (i >= n * KP) return;
    int node = i / KP, k = i - node * KP;
    float v = (k < FIN) ? x[(size_t)node * FIN + k] : 0.f;
    __nv_bfloat16 hi = __float2bfloat16(v);
    g_xhi[i] = hi;
    g_xlo[i] = __float2bfloat16(v - __bfloat162float(hi));
}

__global__ void k_cvtw(const float* __restrict__ W) {
    int i = blockIdx.x * blockDim.x + threadIdx.x;
    if (i >= 256 * KP) return;
    int nc = i / KP, k = i - nc * KP;
    float v = (k < FIN) ? W[(size_t)k * 256 + nc] : 0.f;
    __nv_bfloat16 hi = __float2bfloat16(v);
    g_whiT[i] = hi;
    g_wloT[i] = __float2bfloat16(v - __bfloat162float(hi));
}

// ---------------- tensor-core GEMM1 + fused attention scores ----------------
__device__ __forceinline__ void hmma(float* d, const uint32_t* a, const uint32_t* b) {
    asm volatile(
        "mma.sync.aligned.m16n8k16.row.col.f32.bf16.bf16.f32 "
        "{%0,%1,%2,%3},{%4,%5,%6,%7},{%8,%9},{%0,%1,%2,%3};\n"
        : "+f"(d[0]), "+f"(d[1]), "+f"(d[2]), "+f"(d[3])
        : "r"(a[0]), "r"(a[1]), "r"(a[2]), "r"(a[3]), "r"(b[0]), "r"(b[1]));
}

// block: 128 nodes x 64 cols (= one head). 256 threads = 8 warps (4m x 2n).
__global__ void k_gemm1_mma(const float* __restrict__ att_s, const float* __restrict__ att_d, int n) {
    __shared__ uint32_t sAhi[1024], sAlo[1024], sBhi[512], sBlo[512];
    __shared__ float sS[128], sD[128];
    int bm = blockIdx.y * 128, bn = blockIdx.x * 64, h = bn >> 6;
    int tid = threadIdx.x, lane = tid & 31, wid = tid >> 5;
    int wm = wid & 3, wn = wid >> 2, quad = lane >> 2, t4 = lane & 3;
    if (tid < 128) { sS[tid] = 0.f; sD[tid] = 0.f; }

    const uint32_t* xhi = (const uint32_t*)g_xhi;
    const uint32_t* xlo = (const uint32_t*)g_xlo;
    const uint32_t* whi = (const uint32_t*)g_whiT;
    const uint32_t* wlo = (const uint32_t*)g_wloT;

    float d[2][4][4];
#pragma unroll
    for (int a = 0; a < 2; a++)
#pragma unroll
        for (int b = 0; b < 4; b++)
#pragma unroll
            for (int c = 0; c < 4; c++) d[a][b][c] = 0.f;

    for (int k0 = 0; k0 < KP; k0 += 16) {
        int kw = k0 >> 1;
#pragma unroll
        for (int u = 0; u < 4; u++) {           // A: 128 rows x 8 kwords
            int wd = tid + u * 256;
            int row = wd >> 3, kp = wd & 7;
            int node = bm + row;
            uint32_t vh = 0, vl = 0;
            if (node < n) {
                size_t gi = (size_t)node * KPW + kw + kp;
                vh = xhi[gi]; vl = xlo[gi];
            }
            sAhi[wd] = vh; sAlo[wd] = vl;
        }
#pragma unroll
        for (int u = 0; u < 2; u++) {           // B: 64 cols x 8 kwords
            int wd = tid + u * 256;
            int nr = wd >> 3, kp = wd & 7;
            size_t gi = (size_t)(bn + nr) * KPW + kw + kp;
            sBhi[wd] = whi[gi]; sBlo[wd] = wlo[gi];
        }
        __syncthreads();

        uint32_t ah[2][4], al[2][4], bh[4][2], bl[4][2];
#pragma unroll
        for (int mt = 0; mt < 2; mt++) {
            int r0 = (wm * 32 + mt * 16 + quad) * 8;
            ah[mt][0] = sAhi[r0 + t4];       ah[mt][1] = sAhi[r0 + 64 + t4];
            ah[mt][2] = sAhi[r0 + t4 + 4];   ah[mt][3] = sAhi[r0 + 64 + t4 + 4];
            al[mt][0] = sAlo[r0 + t4];       al[mt][1] = sAlo[r0 + 64 + t4];
            al[mt][2] = sAlo[r0 + t4 + 4];   al[mt][3] = sAlo[r0 + 64 + t4 + 4];
        }
#pragma unroll
        for (int nt = 0; nt < 4; nt++) {
            int c0 = (wn * 32 + nt * 8 + quad) * 8;
            bh[nt][0] = sBhi[c0 + t4]; bh[nt][1] = sBhi[c0 + t4 + 4];
            bl[nt][0] = sBlo[c0 + t4]; bl[nt][1] = sBlo[c0 + t4 + 4];
        }
#pragma unroll
        for (int mt = 0; mt < 2; mt++)
#pragma unroll
            for (int nt = 0; nt < 4; nt++) {
                hmma(d[mt][nt], ah[mt], bh[nt]);
                hmma(d[mt][nt], ah[mt], bl[nt]);
                hmma(d[mt][nt], al[mt], bh[nt]);
            }
        __syncthreads();
    }

    // store h1 (fp16) + accumulate attention-score partial dots
#pragma unroll
    for (int mt = 0; mt < 2; mt++) {
        int row = wm * 32 + mt * 16 + quad;
        int node0 = bm + row, node1 = node0 + 8;
        float s0 = 0.f, s1 = 0.f, dd0 = 0.f, dd1 = 0.f;
#pragma unroll
        for (int nt = 0; nt < 4; nt++) {
            int c = wn * 32 + nt * 8 + t4 * 2;
            float a0 = __ldg(&att_s[h * 64 + c]), a1 = __ldg(&att_s[h * 64 + c + 1]);
            float e0 = __ldg(&att_d[h * 64 + c]), e1 = __ldg(&att_d[h * 64 + c + 1]);
            s0  += d[mt][nt][0] * a0 + d[mt][nt][1] * a1;
            dd0 += d[mt][nt][0] * e0 + d[mt][nt][1] * e1;
            s1  += d[mt][nt][2] * a0 + d[mt][nt][3] * a1;
            dd1 += d[mt][nt][2] * e0 + d[mt][nt][3] * e1;
            if (node0 < n)
                *(__half2*)&g_h1h[(size_t)node0 * F1 + bn + c] = __floats2half2_rn(d[mt][nt][0], d[mt][nt][1]);
            if (node1 < n)
                *(__half2*)&g_h1h[(size_t)node1 * F1 + bn + c] = __floats2half2_rn(d[mt][nt][2], d[mt][nt][3]);
        }
        s0  += __shfl_xor_sync(0xffffffffu, s0, 1);  s0  += __shfl_xor_sync(0xffffffffu, s0, 2);
        s1  += __shfl_xor_sync(0xffffffffu, s1, 1);  s1  += __shfl_xor_sync(0xffffffffu, s1, 2);
        dd0 += __shfl_xor_sync(0xffffffffu, dd0, 1); dd0 += __shfl_xor_sync(0xffffffffu, dd0, 2);
        dd1 += __shfl_xor_sync(0xffffffffu, dd1, 1); dd1 += __shfl_xor_sync(0xffffffffu, dd1, 2);
        if (t4 == 0) {
            atomicAdd(&sS[row], s0); atomicAdd(&sD[row], dd0);
            atomicAdd(&sS[row + 8], s1); atomicAdd(&sD[row + 8], dd1);
        }
    }
    __syncthreads();
    if (tid < 128) {
        int node = bm + tid;
        if (node < n) {
            g_asrc1[node * 4 + h] = sS[tid];
            g_adst1[node * 4 + h] = sD[tid];
        }
    }
}

// ---------------- CSR build (group edges by dst) -----------------------------
__global__ void k_zerocnt(int n) {
    int i = blockIdx.x * blockDim.x + threadIdx.x;
    if (i < n) g_cnt[i] = 0;
}

__global__ void k_count(const int* __restrict__ dst, int e) {
    int i = blockIdx.x * blockDim.x + threadIdx.x;
    if (i < e) atomicAdd(&g_cnt[dst[i]], 1);
}

__global__ void k_scan1(int n) {
    __shared__ int sh[512];
    int t = threadIdx.x, i = blockIdx.x * 512 + t;
    sh[t] = (i < n) ? g_cnt[i] : 0;
    __syncthreads();
    for (int o = 256; o; o >>= 1) {
        if (t < o) sh[t] += sh[t + o];
        __syncthreads();
    }
    if (t == 0) g_bsum[blockIdx.x] = sh[0];
}

__global__ void k_scan2(int n, int nb) {
    __shared__ int sh[256];
    int t = threadIdx.x;
    int own = (t < nb) ? g_bsum[t] : 0;
    sh[t] = own;
    __syncthreads();
    for (int o = 1; o < 256; o <<= 1) {
        int v = (t >= o) ? sh[t - o] : 0;
        __syncthreads();
        sh[t] += v;
        __syncthreads();
    }
    if (t < nb) g_boff[t] = sh[t] - own;
    if (t == nb - 1) g_row[n] = sh[t];
}

__global__ void k_scan3(int n) {
    __shared__ int sh[512];
    int t = threadIdx.x, i = blockIdx.x * 512 + t;
    int own = (i < n) ? g_cnt[i] : 0;
    sh[t] = own;
    __syncthreads();
    for (int o = 1; o < 512; o <<= 1) {
        int v = (t >= o) ? sh[t - o] : 0;
        __syncthreads();
        sh[t] += v;
        __syncthreads();
    }
    if (i < n) {
        int excl = sh[t] - own + g_boff[blockIdx.x];
        g_row[i] = excl;
        g_cur[i] = excl;
    }
}

__global__ void k_scatter(const int* __restrict__ src, const int* __restrict__ dst, int e) {
    int i = blockIdx.x * blockDim.x + threadIdx.x;
    if (i >= e) return;
    int d = dst[i];
    int pos = atomicAdd(&g_cur[d], 1);
    g_esrc[pos] = src[i];
}

// ---------------- softmax stats: warp per node, no atomics ------------------
__global__ void k_msum(int n) {
    int w = (blockIdx.x * blockDim.x + threadIdx.x) >> 5;
    int lane = threadIdx.x & 31;
    if (w >= n) return;
    float4 ad = *(const float4*)&g_adst1[w * 4];
    float m0 = -1e30f, m1 = -1e30f, m2 = -1e30f, m3 = -1e30f;
    float s0 = 0.f, s1 = 0.f, s2 = 0.f, s3 = 0.f;
    if (lane == 0) {   // self-loop
        float4 as = *(const float4*)&g_asrc1[w * 4];
        m0 = lrelu(as.x + ad.x); m1 = lrelu(as.y + ad.y);
        m2 = lrelu(as.z + ad.z); m3 = lrelu(as.w + ad.w);
        s0 = s1 = s2 = s3 = 1.f;
    }
    int beg = g_row[w], end = g_row[w + 1];
    for (int i = beg + lane; i < end; i += 32) {
        int sIdx = __ldg(&g_esrc[i]);
        float4 a = *(const float4*)&g_asrc1[sIdx * 4];
        float e0 = lrelu(a.x + ad.x), e1 = lrelu(a.y + ad.y);
        float e2 = lrelu(a.z + ad.z), e3 = lrelu(a.w + ad.w);
        float nm;
        nm = fmaxf(m0, e0); s0 = s0 * __expf(m0 - nm) + __expf(e0 - nm); m0 = nm;
        nm = fmaxf(m1, e1); s1 = s1 * __expf(m1 - nm) + __expf(e1 - nm); m1 = nm;
        nm = fmaxf(m2, e2); s2 = s2 * __expf(m2 - nm) + __expf(e2 - nm); m2 = nm;
        nm = fmaxf(m3, e3); s3 = s3 * __expf(m3 - nm) + __expf(e3 - nm); m3 = nm;
    }
#pragma unroll
    for (int o = 16; o; o >>= 1) {
        float mm, ss, nm;
        mm = __shfl_xor_sync(0xffffffffu, m0, o); ss = __shfl_xor_sync(0xffffffffu, s0, o);
        nm = fmaxf(m0, mm); s0 = s0 * __expf(m0 - nm) + ss * __expf(mm - nm); m0 = nm;
        mm = __shfl_xor_sync(0xffffffffu, m1, o); ss = __shfl_xor_sync(0xffffffffu, s1, o);
        nm = fmaxf(m1, mm); s1 = s1 * __expf(m1 - nm) + ss * __expf(mm - nm); m1 = nm;
        mm = __shfl_xor_sync(0xffffffffu, m2, o); ss = __shfl_xor_sync(0xffffffffu, s2, o);
        nm = fmaxf(m2, mm); s2 = s2 * __expf(m2 - nm) + ss * __expf(mm - nm); m2 = nm;
        mm = __shfl_xor_sync(0xffffffffu, m3, o); ss = __shfl_xor_sync(0xffffffffu, s3, o);
        nm = fmaxf(m3, mm); s3 = s3 * __expf(m3 - nm) + ss * __expf(mm - nm); m3 = nm;
    }
    if (lane == 0) {
        *(float4*)&g_m1[w * 4]   = make_float4(m0, m1, m2, m3);
        *(float4*)&g_inv1[w * 4] = make_float4(1.f / (s0 + EPSV), 1.f / (s1 + EPSV),
                                               1.f / (s2 + EPSV), 1.f / (s3 + EPSV));
    }
}

// ---- Layer-1 aggregation (precomputed softmax) + fused relu/bias/GEMM2 -----
__global__ void k_agg1f(const float* __restrict__ b1, const float* __restrict__ W2,
                        const float* __restrict__ as2, const float* __restrict__ ad2, int n) {
    int w = (blockIdx.x * blockDim.x + threadIdx.x) >> 5;
    int lane = threadIdx.x & 31;
    if (w >= n) return;
    int h = lane >> 3;
    int ih = w * 4 + h;
    float adst = __ldg(&g_adst1[ih]);
    float m = __ldg(&g_m1[ih]);
    float inv = __ldg(&g_inv1[ih]);

    float acc[8];
    {   // self-loop contribution
        float aSelf = __expf(lrelu(__ldg(&g_asrc1[ih]) + adst) - m) * inv;
        const uint4* sp = (const uint4*)&g_h1h[(size_t)w * F1 + lane * 8];
        uint4 hv = __ldg(sp);
        float2 f0 = __half22float2(*(__half2*)&hv.x);
        float2 f1 = __half22float2(*(__half2*)&hv.y);
        float2 f2 = __half22float2(*(__half2*)&hv.z);
        float2 f3 = __half22float2(*(__half2*)&hv.w);
        acc[0] = aSelf * f0.x; acc[1] = aSelf * f0.y;
        acc[2] = aSelf * f1.x; acc[3] = aSelf * f1.y;
        acc[4] = aSelf * f2.x; acc[5] = aSelf * f2.y;
        acc[6] = aSelf * f3.x; acc[7] = aSelf * f3.y;
    }
    int beg = g_row[w], end = g_row[w + 1];
#pragma unroll 2
    for (int i = beg; i < end; i++) {
        int sIdx = __ldg(&g_esrc[i]);
        float e = lrelu(__ldg(&g_asrc1[sIdx * 4 + h]) + adst);
        float a = __expf(e - m) * inv;
        uint4 hv = __ldg((const uint4*)&g_h1h[(size_t)sIdx * F1 + lane * 8]);
        float2 f0 = __half22float2(*(__half2*)&hv.x);
        float2 f1 = __half22float2(*(__half2*)&hv.y);
        float2 f2 = __half22float2(*(__half2*)&hv.z);
        float2 f3 = __half22float2(*(__half2*)&hv.w);
        acc[0] = fmaf(a, f0.x, acc[0]); acc[1] = fmaf(a, f0.y, acc[1]);
        acc[2] = fmaf(a, f1.x, acc[2]); acc[3] = fmaf(a, f1.y, acc[3]);
        acc[4] = fmaf(a, f2.x, acc[4]); acc[5] = fmaf(a, f2.y, acc[5]);
        acc[6] = fmaf(a, f3.x, acc[6]); acc[7] = fmaf(a, f3.y, acc[7]);
    }
    // fused: h2 = relu(out1 + b1); g = h2 @ W2
    float g0 = 0.f, g1 = 0.f;
#pragma unroll
    for (int j = 0; j < 8; j++) {
        int c = lane * 8 + j;
        float hv = fmaxf(acc[j] + __ldg(&b1[c]), 0.f);
        g0 = fmaf(hv, __ldg(&W2[c * 2 + 0]), g0);
        g1 = fmaf(hv, __ldg(&W2[c * 2 + 1]), g1);
    }
#pragma unroll
    for (int o = 16; o; o >>= 1) {
        g0 += __shfl_down_sync(0xffffffffu, g0, o);
        g1 += __shfl_down_sync(0xffffffffu, g1, o);
    }
    if (lane == 0) {
        g_g[w * 2 + 0] = g0;
        g_g[w * 2 + 1] = g1;
        g_asrc2[w] = g0 * __ldg(&as2[0]) + g1 * __ldg(&as2[1]);
        g_adst2[w] = g0 * __ldg(&ad2[0]) + g1 * __ldg(&ad2[1]);
    }
}

// ---------------- Layer 2 aggregation + bias + log_softmax, fused -----------
__global__ void k_agg2(float* __restrict__ out, const float* __restrict__ b2, int n) {
    int w = (blockIdx.x * blockDim.x + threadIdx.x) >> 5;
    int lane = threadIdx.x & 31;
    if (w >= n) return;
    float adst = g_adst2[w];
    float m = -1e30f, s = 0.f, a0 = 0.f, a1 = 0.f;
    if (lane == 0) {   // self-loop
        m = lrelu(g_asrc2[w] + adst);
        s = 1.f;
        a0 = g_g[w * 2 + 0];
        a1 = g_g[w * 2 + 1];
    }
    int beg = g_row[w], end = g_row[w + 1];
    for (int i = beg + lane; i < end; i += 32) {
        int sIdx = __ldg(&g_esrc[i]);
        float e = lrelu(__ldg(&g_asrc2[sIdx]) + adst);
        float newm = fmaxf(m, e);
        float scale = __expf(m - newm);
        float wgt = __expf(e - newm);
        s = s * scale + wgt;
        a0 = a0 * scale + wgt * __ldg(&g_g[sIdx * 2 + 0]);
        a1 = a1 * scale + wgt * __ldg(&g_g[sIdx * 2 + 1]);
        m = newm;
    }
#pragma unroll
    for (int o = 16; o; o >>= 1) {
        float m2 = __shfl_down_sync(0xffffffffu, m, o);
        float s2 = __shfl_down_sync(0xffffffffu, s, o);
        float b0 = __shfl_down_sync(0xffffffffu, a0, o);
        float b1 = __shfl_down_sync(0xffffffffu, a1, o);
        float newm = fmaxf(m, m2);
        float sc1 = __expf(m - newm);
        float sc2 = __expf(m2 - newm);
        s = s * sc1 + s2 * sc2;
        a0 = a0 * sc1 + b0 * sc2;
        a1 = a1 * sc1 + b1 * sc2;
        m = newm;
    }
    if (lane == 0) {
        float inv = 1.f / (s + EPSV);
        float v0 = a0 * inv + b2[0];
        float v1 = a1 * inv + b2[1];
        float mm = fmaxf(v0, v1);
        float l = logf(expf(v0 - mm) + expf(v1 - mm)) + mm;
        out[w * 2 + 0] = v0 - l;
        out[w * 2 + 1] = v1 - l;
    }
}

// ---------------------------------------------------------------------------
struct GpuSetup {
    cudaStream_t s2;
    cudaEvent_t eFork, eJoin;
    GpuSetup() {
        cudaStreamCreateWithFlags(&s2, cudaStreamNonBlocking);
        cudaEventCreateWithFlags(&eFork, cudaEventDisableTiming);
        cudaEventCreateWithFlags(&eJoin, cudaEventDisableTiming);
    }
};
static GpuSetup g_setup;

extern "C" void kernel_launch(void* const* d_in, const int* in_sizes, int n_in,
                              void* d_out, int out_size) {
    const float* x   = (const float*)d_in[0];
    const int*   src = (const int*)d_in[1];
    const int*   dst = (const int*)d_in[2];
    const float* W1  = (const float*)d_in[3];
    const float* as1 = (const float*)d_in[4];
    const float* ad1 = (const float*)d_in[5];
    const float* b1  = (const float*)d_in[6];
    const float* W2  = (const float*)d_in[7];
    const float* as2 = (const float*)d_in[8];
    const float* ad2 = (const float*)d_in[9];
    const float* b2  = (const float*)d_in[10];
    float* out = (float*)d_out;

    int n = in_sizes[0] / FIN;   // 100000
    int e = in_sizes[1];         // 1600000
    int nb = (n + 511) / 512;    // scan blocks

    // fork: CSR build on side stream, overlapped with convert+GEMM
    cudaEventRecord(g_setup.eFork, 0);
    cudaStreamWaitEvent(g_setup.s2, g_setup.eFork, 0);

    k_zerocnt<<<(n + 255) / 256, 256, 0, g_setup.s2>>>(n);
    k_count<<<(e + 255) / 256, 256, 0, g_setup.s2>>>(dst, e);
    k_scan1<<<nb, 512, 0, g_setup.s2>>>(n);
    k_scan2<<<1, 256, 0, g_setup.s2>>>(n, nb);
    k_scan3<<<nb, 512, 0, g_setup.s2>>>(n);
    k_scatter<<<(e + 255) / 256, 256, 0, g_setup.s2>>>(src, dst, e);
    cudaEventRecord(g_setup.eJoin, g_setup.s2);

    // main stream: bf16 conversion + tensor-core GEMM + fused scores
    k_cvtx<<<(n * KP + 255) / 256, 256>>>(x, n);
    k_cvtw<<<(256 * KP + 255) / 256, 256>>>(W1);
    {
        dim3 grid(4, (n + 127) / 128);
        k_gemm1_mma<<<grid, 256>>>(as1, ad1, n);
    }

    cudaStreamWaitEvent(0, g_setup.eJoin, 0);

    k_msum<<<(n * 32 + 255) / 256, 256>>>(n);
    k_agg1f<<<(n * 32 + 255) / 256, 256>>>(b1, W2, as2, ad2, n);
    k_agg2<<<(n * 32 + 255) / 256, 256>>>(out, b2, n);
}

// round 5
// speedup vs baseline: 6.5197x; 1.1238x over previous
#include <cuda_runtime.h>
#include <cuda_bf16.h>
#include <cuda_fp16.h>
#include <math.h>
#include <stdint.h>

#define NN 100000
#define NE 1600000
#define FIN 165
#define F1  256
#define KP  176            // K padded to multiple of 16
#define KPW (KP/2)         // 32-bit words per row
#define EPSV 1e-16f

// ---------------- scratch (device globals; no allocations allowed) ----------
__device__ __align__(16) __half g_h1h[(size_t)NN * F1];   // fp16 h1 (51 MB)
__device__ __align__(16) float g_asrc1[NN * 4];
__device__ __align__(16) float g_adst1[NN * 4];
__device__ __align__(16) float g_m1[NN * 4];
__device__ __align__(16) float g_inv1[NN * 4];
__device__ __align__(16) float g_g[NN * 2];
__device__ float g_asrc2[NN];
__device__ float g_adst2[NN];
// bf16 operands (x: hi only; W: hi+lo split)
__device__ __align__(16) __nv_bfloat16 g_xhi[(size_t)NN * KP];
__device__ __align__(16) __nv_bfloat16 g_whiT[256 * KP];
__device__ __align__(16) __nv_bfloat16 g_wloT[256 * KP];
// CSR scratch
__device__ int g_cnt[NN];
__device__ int g_row[NN + 1];
__device__ int g_cur[NN];
__device__ int g_esrc[NE];
__device__ int g_bsum[256];
__device__ int g_boff[256];

__device__ __forceinline__ float lrelu(float v) { return v > 0.f ? v : 0.2f * v; }

__device__ __forceinline__ void cpa16(uint32_t dst, const void* src, bool valid) {
    asm volatile("cp.async.cg.shared.global [%0], [%1], 16, %2;\n"
                 :: "r"(dst), "l"(src), "r"(valid ? 16 : 0));
}
__device__ __forceinline__ void cpa_commit() {
    asm volatile("cp.async.commit_group;\n");
}
template <int N>
__device__ __forceinline__ void cpa_wait() {
    asm volatile("cp.async.wait_group %0;\n" :: "n"(N));
}

// ---------------- operand conversion ---------------------------------------
__global__ void k_cvtx(const float* __restrict__ x, int n) {
    int i = blockIdx.x * blockDim.x + threadIdx.x;
    if (i >= n * KP) return;
    int node = i / KP, k = i - node * KP;
    float v = (k < FIN) ? x[(size_t)node * FIN + k] : 0.f;
    g_xhi[i] = __float2bfloat16(v);
}

__global__ void k_cvtw(const float* __restrict__ W) {
    int i = blockIdx.x * blockDim.x + threadIdx.x;
    if (i >= 256 * KP) return;
    int nc = i / KP, k = i - nc * KP;
    float v = (k < FIN) ? W[(size_t)k * 256 + nc] : 0.f;
    __nv_bfloat16 hi = __float2bfloat16(v);
    g_whiT[i] = hi;
    g_wloT[i] = __float2bfloat16(v - __bfloat162float(hi));
}

// ---------------- tensor-core GEMM1 + fused attention scores ----------------
__device__ __forceinline__ void hmma(float* d, const uint32_t* a, const uint32_t* b) {
    asm volatile(
        "mma.sync.aligned.m16n8k16.row.col.f32.bf16.bf16.f32 "
        "{%0,%1,%2,%3},{%4,%5,%6,%7},{%8,%9},{%0,%1,%2,%3};\n"
        : "+f"(d[0]), "+f"(d[1]), "+f"(d[2]), "+f"(d[3])
        : "r"(a[0]), "r"(a[1]), "r"(a[2]), "r"(a[3]), "r"(b[0]), "r"(b[1]));
}

#define ASTRIDE 12          // padded word stride (conflict-free fragment loads)
#define ABUF (128 * ASTRIDE)
#define BBUF (64 * ASTRIDE)
#define NIT  (KP / 16)      // 11 k-iterations

// block: 128 nodes x 64 cols (= one head). 256 threads = 8 warps (4m x 2n).
__global__ void __launch_bounds__(256) k_gemm1_mma(const float* __restrict__ att_s,
                                                   const float* __restrict__ att_d, int n) {
    __shared__ uint32_t sA[2 * ABUF];
    __shared__ uint32_t sBh[2 * BBUF];
    __shared__ uint32_t sBl[2 * BBUF];
    __shared__ float sS[128], sD[128];
    int bm = blockIdx.y * 128, bn = blockIdx.x * 64, h = bn >> 6;
    int tid = threadIdx.x, lane = tid & 31, wid = tid >> 5;
    int wm = wid & 3, wn = wid >> 2, quad = lane >> 2, t4 = lane & 3;
    if (tid < 128) { sS[tid] = 0.f; sD[tid] = 0.f; }

    const uint32_t* xhi = (const uint32_t*)g_xhi;
    const uint32_t* whi = (const uint32_t*)g_whiT;
    const uint32_t* wlo = (const uint32_t*)g_wloT;

    uint32_t sA_b = (uint32_t)__cvta_generic_to_shared(sA);
    uint32_t sBh_b = (uint32_t)__cvta_generic_to_shared(sBh);
    uint32_t sBl_b = (uint32_t)__cvta_generic_to_shared(sBl);

    // tile loaders: A = 128 rows x 8 kwords, B = 64 rows x 8 kwords (hi & lo)
    int a_row = tid >> 1, a_w4 = (tid & 1) * 4;
    int b_row = (tid & 127) >> 1;
    auto loadTile = [&](int it, int buf) {
        int kw = it * 8;
        int node = bm + a_row;
        cpa16(sA_b + (buf * ABUF + a_row * ASTRIDE + a_w4) * 4,
              xhi + (size_t)node * KPW + kw + a_w4, node < n);
        if (tid < 128)
            cpa16(sBh_b + (buf * BBUF + b_row * ASTRIDE + a_w4) * 4,
                  whi + (size_t)(bn + b_row) * KPW + kw + a_w4, true);
        else
            cpa16(sBl_b + (buf * BBUF + b_row * ASTRIDE + a_w4) * 4,
                  wlo + (size_t)(bn + b_row) * KPW + kw + a_w4, true);
        cpa_commit();
    };

    float d[2][4][4];
#pragma unroll
    for (int a = 0; a < 2; a++)
#pragma unroll
        for (int b = 0; b < 4; b++)
#pragma unroll
            for (int c = 0; c < 4; c++) d[a][b][c] = 0.f;

    loadTile(0, 0);

    for (int it = 0; it < NIT; it++) {
        int buf = it & 1;
        if (it + 1 < NIT) loadTile(it + 1, buf ^ 1);
        if (it + 1 < NIT) cpa_wait<1>(); else cpa_wait<0>();
        __syncthreads();

        const uint32_t* cA = sA + buf * ABUF;
        const uint32_t* cBh = sBh + buf * BBUF;
        const uint32_t* cBl = sBl + buf * BBUF;

        uint32_t ah[2][4], bh[4][2], bl[4][2];
#pragma unroll
        for (int mt = 0; mt < 2; mt++) {
            int r0 = (wm * 32 + mt * 16 + quad) * ASTRIDE;
            ah[mt][0] = cA[r0 + t4];                    // (row, k0-7)
            ah[mt][1] = cA[r0 + 8 * ASTRIDE + t4];      // (row+8, k0-7)
            ah[mt][2] = cA[r0 + t4 + 4];                // (row, k8-15)
            ah[mt][3] = cA[r0 + 8 * ASTRIDE + t4 + 4];  // (row+8, k8-15)
        }
#pragma unroll
        for (int nt = 0; nt < 4; nt++) {
            int c0 = (wn * 32 + nt * 8 + quad) * ASTRIDE;
            bh[nt][0] = cBh[c0 + t4]; bh[nt][1] = cBh[c0 + t4 + 4];
            bl[nt][0] = cBl[c0 + t4]; bl[nt][1] = cBl[c0 + t4 + 4];
        }
#pragma unroll
        for (int mt = 0; mt < 2; mt++)
#pragma unroll
            for (int nt = 0; nt < 4; nt++) {
                hmma(d[mt][nt], ah[mt], bh[nt]);
                hmma(d[mt][nt], ah[mt], bl[nt]);
            }
        __syncthreads();   // protect buf before it is overwritten at it+2
    }

    // store h1 (fp16) + accumulate attention-score partial dots
#pragma unroll
    for (int mt = 0; mt < 2; mt++) {
        int row = wm * 32 + mt * 16 + quad;
        int node0 = bm + row, node1 = node0 + 8;
        float s0 = 0.f, s1 = 0.f, dd0 = 0.f, dd1 = 0.f;
#pragma unroll
        for (int nt = 0; nt < 4; nt++) {
            int c = wn * 32 + nt * 8 + t4 * 2;
            float a0 = __ldg(&att_s[h * 64 + c]), a1 = __ldg(&att_s[h * 64 + c + 1]);
            float e0 = __ldg(&att_d[h * 64 + c]), e1 = __ldg(&att_d[h * 64 + c + 1]);
            s0  += d[mt][nt][0] * a0 + d[mt][nt][1] * a1;
            dd0 += d[mt][nt][0] * e0 + d[mt][nt][1] * e1;
            s1  += d[mt][nt][2] * a0 + d[mt][nt][3] * a1;
            dd1 += d[mt][nt][2] * e0 + d[mt][nt][3] * e1;
            if (node0 < n)
                *(__half2*)&g_h1h[(size_t)node0 * F1 + bn + c] = __floats2half2_rn(d[mt][nt][0], d[mt][nt][1]);
            if (node1 < n)
                *(__half2*)&g_h1h[(size_t)node1 * F1 + bn + c] = __floats2half2_rn(d[mt][nt][2], d[mt][nt][3]);
        }
        s0  += __shfl_xor_sync(0xffffffffu, s0, 1);  s0  += __shfl_xor_sync(0xffffffffu, s0, 2);
        s1  += __shfl_xor_sync(0xffffffffu, s1, 1);  s1  += __shfl_xor_sync(0xffffffffu, s1, 2);
        dd0 += __shfl_xor_sync(0xffffffffu, dd0, 1); dd0 += __shfl_xor_sync(0xffffffffu, dd0, 2);
        dd1 += __shfl_xor_sync(0xffffffffu, dd1, 1); dd1 += __shfl_xor_sync(0xffffffffu, dd1, 2);
        if (t4 == 0) {
            atomicAdd(&sS[row], s0); atomicAdd(&sD[row], dd0);
            atomicAdd(&sS[row + 8], s1); atomicAdd(&sD[row + 8], dd1);
        }
    }
    __syncthreads();
    if (tid < 128) {
        int node = bm + tid;
        if (node < n) {
            g_asrc1[node * 4 + h] = sS[tid];
            g_adst1[node * 4 + h] = sD[tid];
        }
    }
}

// ---------------- CSR build (group edges by dst) -----------------------------
__global__ void k_zerocnt(int n) {
    int i = blockIdx.x * blockDim.x + threadIdx.x;
    if (i < n) g_cnt[i] = 0;
}

__global__ void k_count(const int* __restrict__ dst, int e) {
    int i = blockIdx.x * blockDim.x + threadIdx.x;
    if (i < e) atomicAdd(&g_cnt[dst[i]], 1);
}

__global__ void k_scan1(int n) {
    __shared__ int sh[512];
    int t = threadIdx.x, i = blockIdx.x * 512 + t;
    sh[t] = (i < n) ? g_cnt[i] : 0;
    __syncthreads();
    for (int o = 256; o; o >>= 1) {
        if (t < o) sh[t] += sh[t + o];
        __syncthreads();
    }
    if (t == 0) g_bsum[blockIdx.x] = sh[0];
}

__global__ void k_scan2(int n, int nb) {
    __shared__ int sh[256];
    int t = threadIdx.x;
    int own = (t < nb) ? g_bsum[t] : 0;
    sh[t] = own;
    __syncthreads();
    for (int o = 1; o < 256; o <<= 1) {
        int v = (t >= o) ? sh[t - o] : 0;
        __syncthreads();
        sh[t] += v;
        __syncthreads();
    }
    if (t < nb) g_boff[t] = sh[t] - own;
    if (t == nb - 1) g_row[n] = sh[t];
}

__global__ void k_scan3(int n) {
    __shared__ int sh[512];
    int t = threadIdx.x, i = blockIdx.x * 512 + t;
    int own = (i < n) ? g_cnt[i] : 0;
    sh[t] = own;
    __syncthreads();
    for (int o = 1; o < 512; o <<= 1) {
        int v = (t >= o) ? sh[t - o] : 0;
        __syncthreads();
        sh[t] += v;
        __syncthreads();
    }
    if (i < n) {
        int excl = sh[t] - own + g_boff[blockIdx.x];
        g_row[i] = excl;
        g_cur[i] = excl;
    }
}

__global__ void k_scatter(const int* __restrict__ src, const int* __restrict__ dst, int e) {
    int i = blockIdx.x * blockDim.x + threadIdx.x;
    if (i >= e) return;
    int d = dst[i];
    int pos = atomicAdd(&g_cur[d], 1);
    g_esrc[pos] = src[i];
}

// ---------------- softmax stats: warp per node, no atomics ------------------
__global__ void k_msum(int n) {
    int w = (blockIdx.x * blockDim.x + threadIdx.x) >> 5;
    int lane = threadIdx.x & 31;
    if (w >= n) return;
    float4 ad = *(const float4*)&g_adst1[w * 4];
    float m0 = -1e30f, m1 = -1e30f, m2 = -1e30f, m3 = -1e30f;
    float s0 = 0.f, s1 = 0.f, s2 = 0.f, s3 = 0.f;
    if (lane == 0) {   // self-loop
        float4 as = *(const float4*)&g_asrc1[w * 4];
        m0 = lrelu(as.x + ad.x); m1 = lrelu(as.y + ad.y);
        m2 = lrelu(as.z + ad.z); m3 = lrelu(as.w + ad.w);
        s0 = s1 = s2 = s3 = 1.f;
    }
    int beg = g_row[w], end = g_row[w + 1];
    for (int i = beg + lane; i < end; i += 32) {
        int sIdx = __ldg(&g_esrc[i]);
        float4 a = *(const float4*)&g_asrc1[sIdx * 4];
        float e0 = lrelu(a.x + ad.x), e1 = lrelu(a.y + ad.y);
        float e2 = lrelu(a.z + ad.z), e3 = lrelu(a.w + ad.w);
        float nm;
        nm = fmaxf(m0, e0); s0 = s0 * __expf(m0 - nm) + __expf(e0 - nm); m0 = nm;
        nm = fmaxf(m1, e1); s1 = s1 * __expf(m1 - nm) + __expf(e1 - nm); m1 = nm;
        nm = fmaxf(m2, e2); s2 = s2 * __expf(m2 - nm) + __expf(e2 - nm); m2 = nm;
        nm = fmaxf(m3, e3); s3 = s3 * __expf(m3 - nm) + __expf(e3 - nm); m3 = nm;
    }
#pragma unroll
    for (int o = 16; o; o >>= 1) {
        float mm, ss, nm;
        mm = __shfl_xor_sync(0xffffffffu, m0, o); ss = __shfl_xor_sync(0xffffffffu, s0, o);
        nm = fmaxf(m0, mm); s0 = s0 * __expf(m0 - nm) + ss * __expf(mm - nm); m0 = nm;
        mm = __shfl_xor_sync(0xffffffffu, m1, o); ss = __shfl_xor_sync(0xffffffffu, s1, o);
        nm = fmaxf(m1, mm); s1 = s1 * __expf(m1 - nm) + ss * __expf(mm - nm); m1 = nm;
        mm = __shfl_xor_sync(0xffffffffu, m2, o); ss = __shfl_xor_sync(0xffffffffu, s2, o);
        nm = fmaxf(m2, mm); s2 = s2 * __expf(m2 - nm) + ss * __expf(mm - nm); m2 = nm;
        mm = __shfl_xor_sync(0xffffffffu, m3, o); ss = __shfl_xor_sync(0xffffffffu, s3, o);
        nm = fmaxf(m3, mm); s3 = s3 * __expf(m3 - nm) + ss * __expf(mm - nm); m3 = nm;
    }
    if (lane == 0) {
        *(float4*)&g_m1[w * 4]   = make_float4(m0, m1, m2, m3);
        *(float4*)&g_inv1[w * 4] = make_float4(1.f / (s0 + EPSV), 1.f / (s1 + EPSV),
                                               1.f / (s2 + EPSV), 1.f / (s3 + EPSV));
    }
}

// ---- Layer-1 aggregation (precomputed softmax) + fused relu/bias/GEMM2 -----
__global__ void k_agg1f(const float* __restrict__ b1, const float* __restrict__ W2,
                        const float* __restrict__ as2, const float* __restrict__ ad2, int n) {
    int w = (blockIdx.x * blockDim.x + threadIdx.x) >> 5;
    int lane = threadIdx.x & 31;
    if (w >= n) return;
    int h = lane >> 3;
    int ih = w * 4 + h;
    float adst = __ldg(&g_adst1[ih]);
    float m = __ldg(&g_m1[ih]);
    float inv = __ldg(&g_inv1[ih]);

    float acc[8];
    {   // self-loop contribution
        float aSelf = __expf(lrelu(__ldg(&g_asrc1[ih]) + adst) - m) * inv;
        uint4 hv = __ldg((const uint4*)&g_h1h[(size_t)w * F1 + lane * 8]);
        float2 f0 = __half22float2(*(__half2*)&hv.x);
        float2 f1 = __half22float2(*(__half2*)&hv.y);
        float2 f2 = __half22float2(*(__half2*)&hv.z);
        float2 f3 = __half22float2(*(__half2*)&hv.w);
        acc[0] = aSelf * f0.x; acc[1] = aSelf * f0.y;
        acc[2] = aSelf * f1.x; acc[3] = aSelf * f1.y;
        acc[4] = aSelf * f2.x; acc[5] = aSelf * f2.y;
        acc[6] = aSelf * f3.x; acc[7] = aSelf * f3.y;
    }
    int beg = g_row[w], end = g_row[w + 1];
#pragma unroll 2
    for (int i = beg; i < end; i++) {
        int sIdx = __ldg(&g_esrc[i]);
        float e = lrelu(__ldg(&g_asrc1[sIdx * 4 + h]) + adst);
        float a = __expf(e - m) * inv;
        uint4 hv = __ldg((const uint4*)&g_h1h[(size_t)sIdx * F1 + lane * 8]);
        float2 f0 = __half22float2(*(__half2*)&hv.x);
        float2 f1 = __half22float2(*(__half2*)&hv.y);
        float2 f2 = __half22float2(*(__half2*)&hv.z);
        float2 f3 = __half22float2(*(__half2*)&hv.w);
        acc[0] = fmaf(a, f0.x, acc[0]); acc[1] = fmaf(a, f0.y, acc[1]);
        acc[2] = fmaf(a, f1.x, acc[2]); acc[3] = fmaf(a, f1.y, acc[3]);
        acc[4] = fmaf(a, f2.x, acc[4]); acc[5] = fmaf(a, f2.y, acc[5]);
        acc[6] = fmaf(a, f3.x, acc[6]); acc[7] = fmaf(a, f3.y, acc[7]);
    }
    // fused: h2 = relu(out1 + b1); g = h2 @ W2
    float g0 = 0.f, g1 = 0.f;
#pragma unroll
    for (int j = 0; j < 8; j++) {
        int c = lane * 8 + j;
        float hv = fmaxf(acc[j] + __ldg(&b1[c]), 0.f);
        g0 = fmaf(hv, __ldg(&W2[c * 2 + 0]), g0);
        g1 = fmaf(hv, __ldg(&W2[c * 2 + 1]), g1);
    }
#pragma unroll
    for (int o = 16; o; o >>= 1) {
        g0 += __shfl_down_sync(0xffffffffu, g0, o);
        g1 += __shfl_down_sync(0xffffffffu, g1, o);
    }
    if (lane == 0) {
        g_g[w * 2 + 0] = g0;
        g_g[w * 2 + 1] = g1;
        g_asrc2[w] = g0 * __ldg(&as2[0]) + g1 * __ldg(&as2[1]);
        g_adst2[w] = g0 * __ldg(&ad2[0]) + g1 * __ldg(&ad2[1]);
    }
}

// ---------------- Layer 2 aggregation + bias + log_softmax, fused -----------
__global__ void k_agg2(float* __restrict__ out, const float* __restrict__ b2, int n) {
    int w = (blockIdx.x * blockDim.x + threadIdx.x) >> 5;
    int lane = threadIdx.x & 31;
    if (w >= n) return;
    float adst = g_adst2[w];
    float m = -1e30f, s = 0.f, a0 = 0.f, a1 = 0.f;
    if (lane == 0) {   // self-loop
        m = lrelu(g_asrc2[w] + adst);
        s = 1.f;
        a0 = g_g[w * 2 + 0];
        a1 = g_g[w * 2 + 1];
    }
    int beg = g_row[w], end = g_row[w + 1];
    for (int i = beg + lane; i < end; i += 32) {
        int sIdx = __ldg(&g_esrc[i]);
        float e = lrelu(__ldg(&g_asrc2[sIdx]) + adst);
        float newm = fmaxf(m, e);
        float scale = __expf(m - newm);
        float wgt = __expf(e - newm);
        s = s * scale + wgt;
        a0 = a0 * scale + wgt * __ldg(&g_g[sIdx * 2 + 0]);
        a1 = a1 * scale + wgt * __ldg(&g_g[sIdx * 2 + 1]);
        m = newm;
    }
#pragma unroll
    for (int o = 16; o; o >>= 1) {
        float m2 = __shfl_down_sync(0xffffffffu, m, o);
        float s2 = __shfl_down_sync(0xffffffffu, s, o);
        float b0 = __shfl_down_sync(0xffffffffu, a0, o);
        float b1 = __shfl_down_sync(0xffffffffu, a1, o);
        float newm = fmaxf(m, m2);
        float sc1 = __expf(m - newm);
        float sc2 = __expf(m2 - newm);
        s = s * sc1 + s2 * sc2;
        a0 = a0 * sc1 + b0 * sc2;
        a1 = a1 * sc1 + b1 * sc2;
        m = newm;
    }
    if (lane == 0) {
        float inv = 1.f / (s + EPSV);
        float v0 = a0 * inv + b2[0];
        float v1 = a1 * inv + b2[1];
        float mm = fmaxf(v0, v1);
        float l = logf(expf(v0 - mm) + expf(v1 - mm)) + mm;
        out[w * 2 + 0] = v0 - l;
        out[w * 2 + 1] = v1 - l;
    }
}

// ---------------------------------------------------------------------------
struct GpuSetup {
    cudaStream_t s2;
    cudaEvent_t eFork, eJoin;
    GpuSetup() {
        cudaStreamCreateWithFlags(&s2, cudaStreamNonBlocking);
        cudaEventCreateWithFlags(&eFork, cudaEventDisableTiming);
        cudaEventCreateWithFlags(&eJoin, cudaEventDisableTiming);
    }
};
static GpuSetup g_setup;

extern "C" void kernel_launch(void* const* d_in, const int* in_sizes, int n_in,
                              void* d_out, int out_size) {
    const float* x   = (const float*)d_in[0];
    const int*   src = (const int*)d_in[1];
    const int*   dst = (const int*)d_in[2];
    const float* W1  = (const float*)d_in[3];
    const float* as1 = (const float*)d_in[4];
    const float* ad1 = (const float*)d_in[5];
    const float* b1  = (const float*)d_in[6];
    const float* W2  = (const float*)d_in[7];
    const float* as2 = (const float*)d_in[8];
    const float* ad2 = (const float*)d_in[9];
    const float* b2  = (const float*)d_in[10];
    float* out = (float*)d_out;

    int n = in_sizes[0] / FIN;   // 100000
    int e = in_sizes[1];         // 1600000
    int nb = (n + 511) / 512;    // scan blocks

    // fork side stream for CSR build (overlaps convert+GEMM)
    cudaEventRecord(g_setup.eFork, 0);
    cudaStreamWaitEvent(g_setup.s2, g_setup.eFork, 0);

    // issue order chosen so k_gemm1_mma is the 6th kernel launch (ncu -s 5 -c 1)
    k_cvtx<<<(n * KP + 255) / 256, 256>>>(x, n);                       // 0
    k_cvtw<<<(256 * KP + 255) / 256, 256>>>(W1);                       // 1
    k_zerocnt<<<(n + 255) / 256, 256, 0, g_setup.s2>>>(n);             // 2
    k_count<<<(e + 255) / 256, 256, 0, g_setup.s2>>>(dst, e);          // 3
    k_scan1<<<nb, 512, 0, g_setup.s2>>>(n);                            // 4
    {
        dim3 grid(4, (n + 127) / 128);
        k_gemm1_mma<<<grid, 256>>>(as1, ad1, n);                       // 5
    }
    k_scan2<<<1, 256, 0, g_setup.s2>>>(n, nb);                         // 6
    k_scan3<<<nb, 512, 0, g_setup.s2>>>(n);                            // 7
    k_scatter<<<(e + 255) / 256, 256, 0, g_setup.s2>>>(src, dst, e);   // 8
    cudaEventRecord(g_setup.eJoin, g_setup.s2);

    cudaStreamWaitEvent(0, g_setup.eJoin, 0);

    k_msum<<<(n * 32 + 255) / 256, 256>>>(n);                          // 9
    k_agg1f<<<(n * 32 + 255) / 256, 256>>>(b1, W2, as2, ad2, n);       // 10
    k_agg2<<<(n * 32 + 255) / 256, 256>>>(out, b2, n);                 // 11
}

// round 6
// speedup vs baseline: 6.5694x; 1.0076x over previous
#include <cuda_runtime.h>
#include <cuda_bf16.h>
#include <cuda_fp16.h>
#include <math.h>
#include <stdint.h>

#define NN 100000
#define NE 1600000
#define FIN 165
#define F1  256
#define KP  176            // K padded to multiple of 16
#define KPW (KP/2)         // 32-bit words per row
#define EPSV 1e-16f

// ---------------- scratch (device globals; no allocations allowed) ----------
__device__ __align__(16) __half g_h1h[(size_t)NN * F1];   // fp16 h1 (51 MB)
__device__ __align__(16) float g_asrc1[NN * 4];
__device__ __align__(16) float g_adst1[NN * 4];
__device__ __align__(16) float g_m1[NN * 4];
__device__ __align__(16) float g_inv1[NN * 4];
__device__ __align__(16) float g_g[NN * 2];
__device__ float g_asrc2[NN];
__device__ float g_adst2[NN];
// bf16 operands (x: hi only; W: hi+lo split)
__device__ __align__(16) __nv_bfloat16 g_xhi[(size_t)NN * KP];
__device__ __align__(16) __nv_bfloat16 g_whiT[256 * KP];
__device__ __align__(16) __nv_bfloat16 g_wloT[256 * KP];
// CSR scratch
__device__ int g_cnt[NN];
__device__ int g_row[NN + 1];
__device__ int g_cur[NN];
__device__ int g_esrc[NE];
__device__ int g_bsum[256];
__device__ int g_boff[256];

__device__ __forceinline__ float lrelu(float v) { return v > 0.f ? v : 0.2f * v; }

__device__ __forceinline__ void cpa16(uint32_t dst, const void* src, bool valid) {
    asm volatile("cp.async.cg.shared.global [%0], [%1], 16, %2;\n"
                 :: "r"(dst), "l"(src), "r"(valid ? 16 : 0));
}
__device__ __forceinline__ void cpa_commit() {
    asm volatile("cp.async.commit_group;\n");
}
template <int N>
__device__ __forceinline__ void cpa_wait() {
    asm volatile("cp.async.wait_group %0;\n" :: "n"(N));
}

// ---------------- operand conversion ---------------------------------------
__global__ void k_cvtx(const float* __restrict__ x, int n) {
    int i = blockIdx.x * blockDim.x + threadIdx.x;
    if (i >= n * KP) return;
    int node = i / KP, k = i - node * KP;
    float v = (k < FIN) ? __ldg(&x[(size_t)node * FIN + k]) : 0.f;
    g_xhi[i] = __float2bfloat16(v);
}

__global__ void k_cvtw(const float* __restrict__ W) {
    int i = blockIdx.x * blockDim.x + threadIdx.x;
    if (i >= 256 * KP) return;
    int nc = i / KP, k = i - nc * KP;
    float v = (k < FIN) ? W[(size_t)k * 256 + nc] : 0.f;
    __nv_bfloat16 hi = __float2bfloat16(v);
    g_whiT[i] = hi;
    g_wloT[i] = __float2bfloat16(v - __bfloat162float(hi));
}

// ---------------- tensor-core GEMM1 + fused attention scores ----------------
__device__ __forceinline__ void hmma(float* d, const uint32_t* a, const uint32_t* b) {
    asm volatile(
        "mma.sync.aligned.m16n8k16.row.col.f32.bf16.bf16.f32 "
        "{%0,%1,%2,%3},{%4,%5,%6,%7},{%8,%9},{%0,%1,%2,%3};\n"
        : "+f"(d[0]), "+f"(d[1]), "+f"(d[2]), "+f"(d[3])
        : "r"(a[0]), "r"(a[1]), "r"(a[2]), "r"(a[3]), "r"(b[0]), "r"(b[1]));
}

#define ASTRIDE 12          // padded word stride for A (conflict-free frags)
#define ABUF (128 * ASTRIDE)
#define BSTRIDE 92          // 88 kwords + 4 pad, per B row (full K)
#define NIT  (KP / 16)      // 11 k-iterations

// block: 128 nodes x 64 cols (= one head). 256 threads = 8 warps (4m x 2n).
__global__ void __launch_bounds__(256) k_gemm1_mma(const float* __restrict__ att_s,
                                                   const float* __restrict__ att_d, int n) {
    __shared__ uint32_t sA[2 * ABUF];           // 12 KB
    __shared__ uint32_t sBh[64 * BSTRIDE];      // 23 KB
    __shared__ uint32_t sBl[64 * BSTRIDE];      // 23 KB
    __shared__ float sS[128], sD[128];
    int bm = blockIdx.y * 128, bn = blockIdx.x * 64, h = bn >> 6;
    int tid = threadIdx.x, lane = tid & 31, wid = tid >> 5;
    int wm = wid & 3, wn = wid >> 2, quad = lane >> 2, t4 = lane & 3;
    if (tid < 128) { sS[tid] = 0.f; sD[tid] = 0.f; }

    const uint32_t* xhi = (const uint32_t*)g_xhi;
    const uint32_t* whi = (const uint32_t*)g_whiT;
    const uint32_t* wlo = (const uint32_t*)g_wloT;

    uint32_t sA_b = (uint32_t)__cvta_generic_to_shared(sA);
    uint32_t sBh_b = (uint32_t)__cvta_generic_to_shared(sBh);
    uint32_t sBl_b = (uint32_t)__cvta_generic_to_shared(sBl);

    // ---- preload ALL of B (64 rows x 88 kwords, hi+lo) ----
    // 64*88 = 5632 words / 256 threads = 22 words = 5.5 x 16B... do 4B-word strided fill
    {
        // each thread copies words [tid::256] of each array via 16B chunks where aligned
        // simpler: 16B chunks over 5632 words = 1408 chunks, 256 threads -> 5.5; loop 6
        for (int c = tid; c < 1408; c += 256) {
            int rowi = (c * 4) / 88;          // 4 words per chunk, row-major in 88-word rows
            int kw = (c * 4) % 88;
            bool ok = (kw + 4 <= 88);
            // handle row-crossing chunks with scalar fallback
            if (ok) {
                cpa16(sBh_b + (rowi * BSTRIDE + kw) * 4, whi + (size_t)(bn + rowi) * KPW + kw, true);
                cpa16(sBl_b + (rowi * BSTRIDE + kw) * 4, wlo + (size_t)(bn + rowi) * KPW + kw, true);
            } else {
                // 88 % 4 == 0, so chunks never cross rows; ok is always true
            }
        }
        cpa_commit();
    }

    // tile loader for A: 128 rows x 8 kwords, one 16B cp.async per thread
    int a_row = tid >> 1, a_w4 = (tid & 1) * 4;
    auto loadA = [&](int it, int buf) {
        int kw = it * 8;
        int node = bm + a_row;
        cpa16(sA_b + (buf * ABUF + a_row * ASTRIDE + a_w4) * 4,
              xhi + (size_t)node * KPW + kw + a_w4, node < n);
        cpa_commit();
    };

    float d[2][4][4];
#pragma unroll
    for (int a = 0; a < 2; a++)
#pragma unroll
        for (int b = 0; b < 4; b++)
#pragma unroll
            for (int c = 0; c < 4; c++) d[a][b][c] = 0.f;

    loadA(0, 0);
    cpa_wait<0>();
    __syncthreads();

    for (int it = 0; it < NIT; it++) {
        int buf = it & 1;
        if (it + 1 < NIT) loadA(it + 1, buf ^ 1);

        const uint32_t* cA = sA + buf * ABUF;
        int kw = it * 8;

        uint32_t ah[2][4], bh[4][2], bl[4][2];
#pragma unroll
        for (int mt = 0; mt < 2; mt++) {
            int r0 = (wm * 32 + mt * 16 + quad) * ASTRIDE;
            ah[mt][0] = cA[r0 + t4];
            ah[mt][1] = cA[r0 + 8 * ASTRIDE + t4];
            ah[mt][2] = cA[r0 + t4 + 4];
            ah[mt][3] = cA[r0 + 8 * ASTRIDE + t4 + 4];
        }
#pragma unroll
        for (int nt = 0; nt < 4; nt++) {
            int c0 = (wn * 32 + nt * 8 + quad) * BSTRIDE + kw;
            bh[nt][0] = sBh[c0 + t4]; bh[nt][1] = sBh[c0 + t4 + 4];
            bl[nt][0] = sBl[c0 + t4]; bl[nt][1] = sBl[c0 + t4 + 4];
        }
#pragma unroll
        for (int mt = 0; mt < 2; mt++)
#pragma unroll
            for (int nt = 0; nt < 4; nt++) {
                hmma(d[mt][nt], ah[mt], bh[nt]);
                hmma(d[mt][nt], ah[mt], bl[nt]);
            }
        if (it + 1 < NIT) {
            cpa_wait<0>();
            __syncthreads();   // all warps done reading buf; A(it+1) visible
        }
    }

    // store h1 (fp16) + accumulate attention-score partial dots
#pragma unroll
    for (int mt = 0; mt < 2; mt++) {
        int row = wm * 32 + mt * 16 + quad;
        int node0 = bm + row, node1 = node0 + 8;
        float s0 = 0.f, s1 = 0.f, dd0 = 0.f, dd1 = 0.f;
#pragma unroll
        for (int nt = 0; nt < 4; nt++) {
            int c = wn * 32 + nt * 8 + t4 * 2;
            float a0 = __ldg(&att_s[h * 64 + c]), a1 = __ldg(&att_s[h * 64 + c + 1]);
            float e0 = __ldg(&att_d[h * 64 + c]), e1 = __ldg(&att_d[h * 64 + c + 1]);
            s0  += d[mt][nt][0] * a0 + d[mt][nt][1] * a1;
            dd0 += d[mt][nt][0] * e0 + d[mt][nt][1] * e1;
            s1  += d[mt][nt][2] * a0 + d[mt][nt][3] * a1;
            dd1 += d[mt][nt][2] * e0 + d[mt][nt][3] * e1;
            if (node0 < n)
                *(__half2*)&g_h1h[(size_t)node0 * F1 + bn + c] = __floats2half2_rn(d[mt][nt][0], d[mt][nt][1]);
            if (node1 < n)
                *(__half2*)&g_h1h[(size_t)node1 * F1 + bn + c] = __floats2half2_rn(d[mt][nt][2], d[mt][nt][3]);
        }
        s0  += __shfl_xor_sync(0xffffffffu, s0, 1);  s0  += __shfl_xor_sync(0xffffffffu, s0, 2);
        s1  += __shfl_xor_sync(0xffffffffu, s1, 1);  s1  += __shfl_xor_sync(0xffffffffu, s1, 2);
        dd0 += __shfl_xor_sync(0xffffffffu, dd0, 1); dd0 += __shfl_xor_sync(0xffffffffu, dd0, 2);
        dd1 += __shfl_xor_sync(0xffffffffu, dd1, 1); dd1 += __shfl_xor_sync(0xffffffffu, dd1, 2);
        if (t4 == 0) {
            atomicAdd(&sS[row], s0); atomicAdd(&sD[row], dd0);
            atomicAdd(&sS[row + 8], s1); atomicAdd(&sD[row + 8], dd1);
        }
    }
    __syncthreads();
    if (tid < 128) {
        int node = bm + tid;
        if (node < n) {
            g_asrc1[node * 4 + h] = sS[tid];
            g_adst1[node * 4 + h] = sD[tid];
        }
    }
}

// ---------------- CSR build (group edges by dst) -----------------------------
__global__ void k_zerocnt(int n) {
    int i = blockIdx.x * blockDim.x + threadIdx.x;
    if (i < n) g_cnt[i] = 0;
}

__global__ void k_count(const int* __restrict__ dst, int e) {
    int i = blockIdx.x * blockDim.x + threadIdx.x;
    if (i < e) atomicAdd(&g_cnt[dst[i]], 1);
}

__global__ void k_scan1(int n) {
    __shared__ int sh[512];
    int t = threadIdx.x, i = blockIdx.x * 512 + t;
    sh[t] = (i < n) ? g_cnt[i] : 0;
    __syncthreads();
    for (int o = 256; o; o >>= 1) {
        if (t < o) sh[t] += sh[t + o];
        __syncthreads();
    }
    if (t == 0) g_bsum[blockIdx.x] = sh[0];
}

__global__ void k_scan2(int n, int nb) {
    __shared__ int sh[256];
    int t = threadIdx.x;
    int own = (t < nb) ? g_bsum[t] : 0;
    sh[t] = own;
    __syncthreads();
    for (int o = 1; o < 256; o <<= 1) {
        int v = (t >= o) ? sh[t - o] : 0;
        __syncthreads();
        sh[t] += v;
        __syncthreads();
    }
    if (t < nb) g_boff[t] = sh[t] - own;
    if (t == nb - 1) g_row[n] = sh[t];
}

__global__ void k_scan3(int n) {
    __shared__ int sh[512];
    int t = threadIdx.x, i = blockIdx.x * 512 + t;
    int own = (i < n) ? g_cnt[i] : 0;
    sh[t] = own;
    __syncthreads();
    for (int o = 1; o < 512; o <<= 1) {
        int v = (t >= o) ? sh[t - o] : 0;
        __syncthreads();
        sh[t] += v;
        __syncthreads();
    }
    if (i < n) {
        int excl = sh[t] - own + g_boff[blockIdx.x];
        g_row[i] = excl;
        g_cur[i] = excl;
    }
}

__global__ void k_scatter(const int* __restrict__ src, const int* __restrict__ dst, int e) {
    int i = blockIdx.x * blockDim.x + threadIdx.x;
    if (i >= e) return;
    int d = dst[i];
    int pos = atomicAdd(&g_cur[d], 1);
    g_esrc[pos] = src[i];
}

// ---------------- softmax stats: warp per node, no atomics ------------------
__global__ void k_msum(int n) {
    int w = (blockIdx.x * blockDim.x + threadIdx.x) >> 5;
    int lane = threadIdx.x & 31;
    if (w >= n) return;
    float4 ad = *(const float4*)&g_adst1[w * 4];
    float m0 = -1e30f, m1 = -1e30f, m2 = -1e30f, m3 = -1e30f;
    float s0 = 0.f, s1 = 0.f, s2 = 0.f, s3 = 0.f;
    if (lane == 0) {   // self-loop
        float4 as = *(const float4*)&g_asrc1[w * 4];
        m0 = lrelu(as.x + ad.x); m1 = lrelu(as.y + ad.y);
        m2 = lrelu(as.z + ad.z); m3 = lrelu(as.w + ad.w);
        s0 = s1 = s2 = s3 = 1.f;
    }
    int beg = g_row[w], end = g_row[w + 1];
    for (int i = beg + lane; i < end; i += 32) {
        int sIdx = __ldg(&g_esrc[i]);
        float4 a = *(const float4*)&g_asrc1[sIdx * 4];
        float e0 = lrelu(a.x + ad.x), e1 = lrelu(a.y + ad.y);
        float e2 = lrelu(a.z + ad.z), e3 = lrelu(a.w + ad.w);
        float nm;
        nm = fmaxf(m0, e0); s0 = s0 * __expf(m0 - nm) + __expf(e0 - nm); m0 = nm;
        nm = fmaxf(m1, e1); s1 = s1 * __expf(m1 - nm) + __expf(e1 - nm); m1 = nm;
        nm = fmaxf(m2, e2); s2 = s2 * __expf(m2 - nm) + __expf(e2 - nm); m2 = nm;
        nm = fmaxf(m3, e3); s3 = s3 * __expf(m3 - nm) + __expf(e3 - nm); m3 = nm;
    }
#pragma unroll
    for (int o = 16; o; o >>= 1) {
        float mm, ss, nm;
        mm = __shfl_xor_sync(0xffffffffu, m0, o); ss = __shfl_xor_sync(0xffffffffu, s0, o);
        nm = fmaxf(m0, mm); s0 = s0 * __expf(m0 - nm) + ss * __expf(mm - nm); m0 = nm;
        mm = __shfl_xor_sync(0xffffffffu, m1, o); ss = __shfl_xor_sync(0xffffffffu, s1, o);
        nm = fmaxf(m1, mm); s1 = s1 * __expf(m1 - nm) + ss * __expf(mm - nm); m1 = nm;
        mm = __shfl_xor_sync(0xffffffffu, m2, o); ss = __shfl_xor_sync(0xffffffffu, s2, o);
        nm = fmaxf(m2, mm); s2 = s2 * __expf(m2 - nm) + ss * __expf(mm - nm); m2 = nm;
        mm = __shfl_xor_sync(0xffffffffu, m3, o); ss = __shfl_xor_sync(0xffffffffu, s3, o);
        nm = fmaxf(m3, mm); s3 = s3 * __expf(m3 - nm) + ss * __expf(mm - nm); m3 = nm;
    }
    if (lane == 0) {
        *(float4*)&g_m1[w * 4]   = make_float4(m0, m1, m2, m3);
        *(float4*)&g_inv1[w * 4] = make_float4(1.f / (s0 + EPSV), 1.f / (s1 + EPSV),
                                               1.f / (s2 + EPSV), 1.f / (s3 + EPSV));
    }
}

// ---- Layer-1 aggregation (precomputed softmax) + fused relu/bias/GEMM2 -----
__global__ void k_agg1f(const float* __restrict__ b1, const float* __restrict__ W2,
                        const float* __restrict__ as2, const float* __restrict__ ad2, int n) {
    int w = (blockIdx.x * blockDim.x + threadIdx.x) >> 5;
    int lane = threadIdx.x & 31;
    if (w >= n) return;
    int h = lane >> 3;
    int ih = w * 4 + h;
    float adst = __ldg(&g_adst1[ih]);
    float m = __ldg(&g_m1[ih]);
    float inv = __ldg(&g_inv1[ih]);

    float acc[8];
    {   // self-loop contribution
        float aSelf = __expf(lrelu(__ldg(&g_asrc1[ih]) + adst) - m) * inv;
        uint4 hv = __ldg((const uint4*)&g_h1h[(size_t)w * F1 + lane * 8]);
        float2 f0 = __half22float2(*(__half2*)&hv.x);
        float2 f1 = __half22float2(*(__half2*)&hv.y);
        float2 f2 = __half22float2(*(__half2*)&hv.z);
        float2 f3 = __half22float2(*(__half2*)&hv.w);
        acc[0] = aSelf * f0.x; acc[1] = aSelf * f0.y;
        acc[2] = aSelf * f1.x; acc[3] = aSelf * f1.y;
        acc[4] = aSelf * f2.x; acc[5] = aSelf * f2.y;
        acc[6] = aSelf * f3.x; acc[7] = aSelf * f3.y;
    }
    int beg = g_row[w], end = g_row[w + 1];
    int i = beg;
    // 2-edge software pipeline: two independent row loads in flight
    for (; i + 1 < end; i += 2) {
        int sA = __ldg(&g_esrc[i]);
        int sB = __ldg(&g_esrc[i + 1]);
        float eA = lrelu(__ldg(&g_asrc1[sA * 4 + h]) + adst);
        float eB = lrelu(__ldg(&g_asrc1[sB * 4 + h]) + adst);
        uint4 hvA = __ldg((const uint4*)&g_h1h[(size_t)sA * F1 + lane * 8]);
        uint4 hvB = __ldg((const uint4*)&g_h1h[(size_t)sB * F1 + lane * 8]);
        float aA = __expf(eA - m) * inv;
        float aB = __expf(eB - m) * inv;
        float2 a0 = __half22float2(*(__half2*)&hvA.x);
        float2 a1 = __half22float2(*(__half2*)&hvA.y);
        float2 a2 = __half22float2(*(__half2*)&hvA.z);
        float2 a3 = __half22float2(*(__half2*)&hvA.w);
        float2 b0 = __half22float2(*(__half2*)&hvB.x);
        float2 b1v = __half22float2(*(__half2*)&hvB.y);
        float2 b2v = __half22float2(*(__half2*)&hvB.z);
        float2 b3 = __half22float2(*(__half2*)&hvB.w);
        acc[0] = fmaf(aA, a0.x, fmaf(aB, b0.x, acc[0]));
        acc[1] = fmaf(aA, a0.y, fmaf(aB, b0.y, acc[1]));
        acc[2] = fmaf(aA, a1.x, fmaf(aB, b1v.x, acc[2]));
        acc[3] = fmaf(aA, a1.y, fmaf(aB, b1v.y, acc[3]));
        acc[4] = fmaf(aA, a2.x, fmaf(aB, b2v.x, acc[4]));
        acc[5] = fmaf(aA, a2.y, fmaf(aB, b2v.y, acc[5]));
        acc[6] = fmaf(aA, a3.x, fmaf(aB, b3.x, acc[6]));
        acc[7] = fmaf(aA, a3.y, fmaf(aB, b3.y, acc[7]));
    }
    if (i < end) {
        int sA = __ldg(&g_esrc[i]);
        float eA = lrelu(__ldg(&g_asrc1[sA * 4 + h]) + adst);
        float aA = __expf(eA - m) * inv;
        uint4 hv = __ldg((const uint4*)&g_h1h[(size_t)sA * F1 + lane * 8]);
        float2 f0 = __half22float2(*(__half2*)&hv.x);
        float2 f1 = __half22float2(*(__half2*)&hv.y);
        float2 f2 = __half22float2(*(__half2*)&hv.z);
        float2 f3 = __half22float2(*(__half2*)&hv.w);
        acc[0] = fmaf(aA, f0.x, acc[0]); acc[1] = fmaf(aA, f0.y, acc[1]);
        acc[2] = fmaf(aA, f1.x, acc[2]); acc[3] = fmaf(aA, f1.y, acc[3]);
        acc[4] = fmaf(aA, f2.x, acc[4]); acc[5] = fmaf(aA, f2.y, acc[5]);
        acc[6] = fmaf(aA, f3.x, acc[6]); acc[7] = fmaf(aA, f3.y, acc[7]);
    }
    // fused: h2 = relu(out1 + b1); g = h2 @ W2
    float g0 = 0.f, g1 = 0.f;
#pragma unroll
    for (int j = 0; j < 8; j++) {
        int c = lane * 8 + j;
        float hv = fmaxf(acc[j] + __ldg(&b1[c]), 0.f);
        g0 = fmaf(hv, __ldg(&W2[c * 2 + 0]), g0);
        g1 = fmaf(hv, __ldg(&W2[c * 2 + 1]), g1);
    }
#pragma unroll
    for (int o = 16; o; o >>= 1) {
        g0 += __shfl_down_sync(0xffffffffu, g0, o);
        g1 += __shfl_down_sync(0xffffffffu, g1, o);
    }
    if (lane == 0) {
        g_g[w * 2 + 0] = g0;
        g_g[w * 2 + 1] = g1;
        g_asrc2[w] = g0 * __ldg(&as2[0]) + g1 * __ldg(&as2[1]);
        g_adst2[w] = g0 * __ldg(&ad2[0]) + g1 * __ldg(&ad2[1]);
    }
}

// ---------------- Layer 2 aggregation + bias + log_softmax, fused -----------
__global__ void k_agg2(float* __restrict__ out, const float* __restrict__ b2, int n) {
    int w = (blockIdx.x * blockDim.x + threadIdx.x) >> 5;
    int lane = threadIdx.x & 31;
    if (w >= n) return;
    float adst = g_adst2[w];
    float m = -1e30f, s = 0.f, a0 = 0.f, a1 = 0.f;
    if (lane == 0) {   // self-loop
        m = lrelu(g_asrc2[w] + adst);
        s = 1.f;
        a0 = g_g[w * 2 + 0];
        a1 = g_g[w * 2 + 1];
    }
    int beg = g_row[w], end = g_row[w + 1];
    for (int i = beg + lane; i < end; i += 32) {
        int sIdx = __ldg(&g_esrc[i]);
        float e = lrelu(__ldg(&g_asrc2[sIdx]) + adst);
        float newm = fmaxf(m, e);
        float scale = __expf(m - newm);
        float wgt = __expf(e - newm);
        s = s * scale + wgt;
        a0 = a0 * scale + wgt * __ldg(&g_g[sIdx * 2 + 0]);
        a1 = a1 * scale + wgt * __ldg(&g_g[sIdx * 2 + 1]);
        m = newm;
    }
#pragma unroll
    for (int o = 16; o; o >>= 1) {
        float m2 = __shfl_down_sync(0xffffffffu, m, o);
        float s2 = __shfl_down_sync(0xffffffffu, s, o);
        float b0 = __shfl_down_sync(0xffffffffu, a0, o);
        float b1 = __shfl_down_sync(0xffffffffu, a1, o);
        float newm = fmaxf(m, m2);
        float sc1 = __expf(m - newm);
        float sc2 = __expf(m2 - newm);
        s = s * sc1 + s2 * sc2;
        a0 = a0 * sc1 + b0 * sc2;
        a1 = a1 * sc1 + b1 * sc2;
        m = newm;
    }
    if (lane == 0) {
        float inv = 1.f / (s + EPSV);
        float v0 = a0 * inv + b2[0];
        float v1 = a1 * inv + b2[1];
        float mm = fmaxf(v0, v1);
        float l = logf(expf(v0 - mm) + expf(v1 - mm)) + mm;
        out[w * 2 + 0] = v0 - l;
        out[w * 2 + 1] = v1 - l;
    }
}

// ---------------------------------------------------------------------------
struct GpuSetup {
    cudaStream_t s2;
    cudaEvent_t eFork, eJoin;
    GpuSetup() {
        cudaStreamCreateWithFlags(&s2, cudaStreamNonBlocking);
        cudaEventCreateWithFlags(&eFork, cudaEventDisableTiming);
        cudaEventCreateWithFlags(&eJoin, cudaEventDisableTiming);
    }
};
static GpuSetup g_setup;

extern "C" void kernel_launch(void* const* d_in, const int* in_sizes, int n_in,
                              void* d_out, int out_size) {
    const float* x   = (const float*)d_in[0];
    const int*   src = (const int*)d_in[1];
    const int*   dst = (const int*)d_in[2];
    const float* W1  = (const float*)d_in[3];
    const float* as1 = (const float*)d_in[4];
    const float* ad1 = (const float*)d_in[5];
    const float* b1  = (const float*)d_in[6];
    const float* W2  = (const float*)d_in[7];
    const float* as2 = (const float*)d_in[8];
    const float* ad2 = (const float*)d_in[9];
    const float* b2  = (const float*)d_in[10];
    float* out = (float*)d_out;

    int n = in_sizes[0] / FIN;   // 100000
    int e = in_sizes[1];         // 1600000
    int nb = (n + 511) / 512;    // scan blocks

    // fork side stream for CSR build (overlaps convert+GEMM)
    cudaEventRecord(g_setup.eFork, 0);
    cudaStreamWaitEvent(g_setup.s2, g_setup.eFork, 0);

    // issue order: slot #3 = k_gemm1_mma (ncu empirically profiles the 4th launch)
    k_cvtx<<<(n * KP + 255) / 256, 256>>>(x, n);                       // 0
    k_cvtw<<<(256 * KP + 255) / 256, 256>>>(W1);                       // 1
    k_zerocnt<<<(n + 255) / 256, 256, 0, g_setup.s2>>>(n);             // 2
    {
        dim3 grid(4, (n + 127) / 128);
        k_gemm1_mma<<<grid, 256>>>(as1, ad1, n);                       // 3  <-- profiled
    }
    k_count<<<(e + 255) / 256, 256, 0, g_setup.s2>>>(dst, e);          // 4
    k_scan1<<<nb, 512, 0, g_setup.s2>>>(n);                            // 5
    k_scan2<<<1, 256, 0, g_setup.s2>>>(n, nb);                         // 6
    k_scan3<<<nb, 512, 0, g_setup.s2>>>(n);                            // 7
    k_scatter<<<(e + 255) / 256, 256, 0, g_setup.s2>>>(src, dst, e);   // 8
    cudaEventRecord(g_setup.eJoin, g_setup.s2);

    cudaStreamWaitEvent(0, g_setup.eJoin, 0);

    k_msum<<<(n * 32 + 255) / 256, 256>>>(n);                          // 9
    k_agg1f<<<(n * 32 + 255) / 256, 256>>>(b1, W2, as2, ad2, n);       // 10
    k_agg2<<<(n * 32 + 255) / 256, 256>>>(out, b2, n);                 // 11
}